// round 12
// baseline (speedup 1.0000x reference)
#include <cuda_runtime.h>
#include <math.h>

#define BB 1024
#define CC 64
#define DD 256
#define NN 512
#define K2 (2*DD)
#define DELTA 1e-4f

// pre-split A plane: [b][k] stacked x_in | 0.3*x_ctx as (hi,lo)
__device__ float2 g_A2[BB * K2];
__device__ float  g_boost[CC * NN];

// ---- tf32 split ----
__device__ __forceinline__ float2 split1(float f) {
    unsigned h;
    asm("cvt.rna.tf32.f32 %0, %1;" : "=r"(h) : "f"(f));
    float hf = __uint_as_float(h);
    return make_float2(hf, f - hf);
}
__device__ __forceinline__ void mma_tf32(
    float& c0, float& c1, float& c2, float& c3,
    unsigned a0, unsigned a1, unsigned a2, unsigned a3,
    unsigned b0, unsigned b1)
{
    asm("mma.sync.aligned.m16n8k8.row.col.f32.tf32.tf32.f32 "
        "{%0,%1,%2,%3},{%4,%5,%6,%7},{%8,%9},{%0,%1,%2,%3};"
        : "+f"(c0), "+f"(c1), "+f"(c2), "+f"(c3)
        : "r"(a0), "r"(a1), "r"(a2), "r"(a3), "r"(b0), "r"(b1));
}

// ---------------------------------------------------------------------------
// prep kernels
// ---------------------------------------------------------------------------
__global__ void boost_kernel(const float* __restrict__ avg) {
    int i = blockIdx.x * blockDim.x + threadIdx.x;
    if (i < CC * NN) g_boost[i] = log1pf(0.05f / (avg[i] + 1e-6f));
}

__global__ void prep_A(const float* __restrict__ x_in, const float* __restrict__ x_ctx) {
    int i = blockIdx.x * blockDim.x + threadIdx.x;
    if (i < BB * K2) {
        int b = i >> 9, k = i & (K2 - 1);
        float v = (k < DD) ? x_in[(b << 8) + k] : 0.3f * x_ctx[(b << 8) + k - DD];
        g_A2[i] = split1(v);
    }
}

// ---------------------------------------------------------------------------
// Kernel 1: drive GEMM, 3xTF32. Round-7 skeleton (BK=16, double-buffered),
// but both operands pre-split into float2 smem so the mainloop is pure
// LDS.64 + MMA. Layouts [k][x] float2, stride 132 (mod16==4 -> conflict-free).
// ---------------------------------------------------------------------------
#define AB_LD  132                 // float2 stride per k-row
#define AB_BUF (16 * AB_LD)        // float2 per buffer (one plane)
#define DRIVE_SMEM (4 * AB_BUF * (int)sizeof(float2))   // 2 bufs x (A+B)

__global__ __launch_bounds__(256) void drive_gemm(
    const float* __restrict__ Wff, const float* __restrict__ Wctx,
    const float* __restrict__ bias, float* __restrict__ act)
{
    extern __shared__ float2 dsm[];
    float2* As2 = dsm;               // [2][16][AB_LD]
    float2* Bs2 = dsm + 2 * AB_BUF;  // [2][16][AB_LD]

    int c  = blockIdx.z;
    int m0 = blockIdx.y * 128;
    int n0 = blockIdx.x * 128;
    int tid  = threadIdx.x;
    int warp = tid >> 5, lane = tid & 31;
    int wm = (warp & 1) * 64;
    int wn = (warp >> 1) * 32;
    int ar = lane >> 2;
    int ac = lane & 3;

    // loader coords
    int am  = tid >> 1, akq = (tid & 1) * 8;   // A: m-row am, k-offset akq (float2 units)

    float acc[16][4];
    #pragma unroll
    for (int i = 0; i < 16; i++)
        #pragma unroll
        for (int j = 0; j < 4; j++) acc[i][j] = 0.f;

    const float* WffC  = Wff  + (size_t)c * DD * NN;
    const float* WctxC = Wctx + (size_t)c * DD * NN;
    const float2* gA   = g_A2 + (size_t)(m0 + am) * K2 + akq;

    // ---- preload k-tile 0 ----
    {
        const float4* pA = reinterpret_cast<const float4*>(gA);
        #pragma unroll
        for (int i = 0; i < 4; i++) {
            float4 v = pA[i];
            As2[(akq + 2*i    ) * AB_LD + am] = make_float2(v.x, v.y);
            As2[(akq + 2*i + 1) * AB_LD + am] = make_float2(v.z, v.w);
        }
        #pragma unroll
        for (int i = 0; i < 2; i++) {
            int t = tid + i * 256;
            int kk = t >> 5, nq = (t & 31) << 2;
            float4 wv = *reinterpret_cast<const float4*>(WffC + (size_t)kk * NN + n0 + nq);
            float2 s0 = split1(wv.x), s1 = split1(wv.y), s2 = split1(wv.z), s3 = split1(wv.w);
            float4* dst = reinterpret_cast<float4*>(&Bs2[kk * AB_LD + nq]);
            dst[0] = make_float4(s0.x, s0.y, s1.x, s1.y);
            dst[1] = make_float4(s2.x, s2.y, s3.x, s3.y);
        }
    }
    __syncthreads();

    int cur = 0;
    for (int kt = 0; kt < K2 / 16; kt++) {
        float4 pa[4], pb[2];
        bool has_next = (kt + 1 < K2 / 16);
        if (has_next) {
            int k0 = (kt + 1) * 16;
            const float4* pA = reinterpret_cast<const float4*>(gA + k0);
            #pragma unroll
            for (int i = 0; i < 4; i++) pa[i] = pA[i];
            const float* wsrc = (k0 < DD) ? (WffC + (size_t)k0 * NN)
                                          : (WctxC + (size_t)(k0 - DD) * NN);
            #pragma unroll
            for (int i = 0; i < 2; i++) {
                int t = tid + i * 256;
                int kk = t >> 5, nq = (t & 31) << 2;
                pb[i] = *reinterpret_cast<const float4*>(wsrc + (size_t)kk * NN + n0 + nq);
            }
        }

        const float2* Ab = As2 + cur * AB_BUF;
        const float2* Bb = Bs2 + cur * AB_BUF;

        #pragma unroll
        for (int kh = 0; kh < 2; kh++) {
            int kk0 = kh * 8;
            unsigned bh[8], bl[8];
            #pragma unroll
            for (int sn = 0; sn < 4; sn++) {
                float2 b0 = Bb[(kk0 + ac    ) * AB_LD + wn + sn * 8 + ar];
                float2 b1 = Bb[(kk0 + ac + 4) * AB_LD + wn + sn * 8 + ar];
                bh[sn*2+0] = __float_as_uint(b0.x); bl[sn*2+0] = __float_as_uint(b0.y);
                bh[sn*2+1] = __float_as_uint(b1.x); bl[sn*2+1] = __float_as_uint(b1.y);
            }
            #pragma unroll
            for (int sm = 0; sm < 4; sm++) {
                int mb = wm + sm * 16;
                float2 A0 = Ab[(kk0 + ac    ) * AB_LD + mb + ar];
                float2 A1 = Ab[(kk0 + ac    ) * AB_LD + mb + ar + 8];
                float2 A2 = Ab[(kk0 + ac + 4) * AB_LD + mb + ar];
                float2 A3 = Ab[(kk0 + ac + 4) * AB_LD + mb + ar + 8];
                unsigned ah0 = __float_as_uint(A0.x), al0 = __float_as_uint(A0.y);
                unsigned ah1 = __float_as_uint(A1.x), al1 = __float_as_uint(A1.y);
                unsigned ah2 = __float_as_uint(A2.x), al2 = __float_as_uint(A2.y);
                unsigned ah3 = __float_as_uint(A3.x), al3 = __float_as_uint(A3.y);
                #pragma unroll
                for (int sn = 0; sn < 4; sn++) {
                    float* cp = acc[sm * 4 + sn];
                    mma_tf32(cp[0], cp[1], cp[2], cp[3],
                             ah0, ah1, ah2, ah3, bh[sn*2], bh[sn*2+1]);
                    mma_tf32(cp[0], cp[1], cp[2], cp[3],
                             ah0, ah1, ah2, ah3, bl[sn*2], bl[sn*2+1]);
                    mma_tf32(cp[0], cp[1], cp[2], cp[3],
                             al0, al1, al2, al3, bh[sn*2], bh[sn*2+1]);
                }
            }
        }

        if (has_next) {
            int nxt = cur ^ 1;
            #pragma unroll
            for (int i = 0; i < 4; i++) {
                As2[nxt * AB_BUF + (akq + 2*i    ) * AB_LD + am] = make_float2(pa[i].x, pa[i].y);
                As2[nxt * AB_BUF + (akq + 2*i + 1) * AB_LD + am] = make_float2(pa[i].z, pa[i].w);
            }
            #pragma unroll
            for (int i = 0; i < 2; i++) {
                int t = tid + i * 256;
                int kk = t >> 5, nq = (t & 31) << 2;
                float2 s0 = split1(pb[i].x), s1 = split1(pb[i].y);
                float2 s2 = split1(pb[i].z), s3 = split1(pb[i].w);
                float4* dst = reinterpret_cast<float4*>(&Bs2[nxt * AB_BUF + kk * AB_LD + nq]);
                dst[0] = make_float4(s0.x, s0.y, s1.x, s1.y);
                dst[1] = make_float4(s2.x, s2.y, s3.x, s3.y);
            }
            __syncthreads();
            cur = nxt;
        }
    }

    // ---- epilogue: + bias, scatter ----
    const float* bc = bias + (size_t)c * NN;
    #pragma unroll
    for (int sm = 0; sm < 4; sm++) {
        #pragma unroll
        for (int sn = 0; sn < 4; sn++) {
            const float* cp = acc[sm * 4 + sn];
            int col = n0 + wn + sn * 8 + ac * 2;
            float bx = bc[col], by = bc[col + 1];
            int r0 = m0 + wm + sm * 16 + ar;
            float2 v0 = make_float2(cp[0] + bx, cp[1] + by);
            float2 v1 = make_float2(cp[2] + bx, cp[3] + by);
            *reinterpret_cast<float2*>(act + ((size_t)r0 * CC + c) * NN + col)       = v0;
            *reinterpret_cast<float2*>(act + ((size_t)(r0 + 8) * CC + c) * NN + col) = v1;
        }
    }
}

// ---------------------------------------------------------------------------
// Kernel 2: warp-per-row k-WTA, margin-exact, float-bisection threshold.
// ---------------------------------------------------------------------------
__device__ __forceinline__ unsigned f2ord(float f) {
    unsigned u = __float_as_uint(f);
    return (u & 0x80000000u) ? ~u : (u | 0x80000000u);
}
__device__ __forceinline__ float ord2f(unsigned u) {
    unsigned v = (u & 0x80000000u) ? (u & 0x7FFFFFFFu) : ~u;
    return __uint_as_float(v);
}

__global__ __launch_bounds__(256, 4) void topk_pred(
    const int* __restrict__ kptr, const float* __restrict__ x_in,
    const float* __restrict__ x_ctx,
    const float* __restrict__ Wff, const float* __restrict__ Wctx,
    const float* __restrict__ bias,
    const float* __restrict__ Wp,
    float* __restrict__ act, float* __restrict__ pred, float* __restrict__ err)
{
    int lane = threadIdx.x & 31;
    int w    = threadIdx.x >> 5;
    int row  = blockIdx.x * 8 + w;          // b*C + c
    int c = row & (CC - 1);
    int b = row >> 6;

    __shared__ float s_vv[8][64];
    __shared__ int   s_ii[8][64];
    __shared__ int   s_bi[8][32];     // borderline column indices (rare path)
    __shared__ float s_be[8][32];     // borderline exact boosted values
    __shared__ unsigned s_bm[8][16];  // rare-path winner bitmap (512 bits)

    const float4* arow = reinterpret_cast<const float4*>(act + (size_t)row * NN);
    const float4* brow = reinterpret_cast<const float4*>(g_boost + (size_t)c * NN);

    float    f[16];
    unsigned u[16];
    #pragma unroll
    for (int i = 0; i < 4; i++) {
        float4 a  = arow[i * 32 + lane];
        float4 bo = brow[i * 32 + lane];
        f[i*4+0] = a.x; f[i*4+1] = a.y; f[i*4+2] = a.z; f[i*4+3] = a.w;
        u[i*4+0] = f2ord(a.x + bo.x);
        u[i*4+1] = f2ord(a.y + bo.y);
        u[i*4+2] = f2ord(a.z + bo.z);
        u[i*4+3] = f2ord(a.w + bo.w);
    }

    int k = *kptr;

    // ---- range: [min-of-lane-maxes (k<=32) or global min, max] ----
    unsigned lmax = 0, lmin = 0xFFFFFFFFu;
    #pragma unroll
    for (int s = 0; s < 16; s++) { lmax = max(lmax, u[s]); lmin = min(lmin, u[s]); }
    unsigned mx = lmax, lb = lmax, gmn = lmin;
    #pragma unroll
    for (int o = 16; o; o >>= 1) {
        mx  = max(mx,  __shfl_xor_sync(0xffffffffu, mx,  o));
        lb  = min(lb,  __shfl_xor_sync(0xffffffffu, lb,  o));
        gmn = min(gmn, __shfl_xor_sync(0xffffffffu, gmn, o));
    }
    if (k > 32) lb = gmn;

    // ---- float bisection: lo s.t. cnt(>=lo) >= k, hi s.t. cnt(>=hi) < k ----
    float lof = ord2f(lb);
    float hif = ord2f(mx + 1u);
    int it = 0;
    while (hif - lof > 2.5e-5f && it < 40) {
        float midf = 0.5f * (lof + hif);
        unsigned Um = f2ord(midf);
        int cnt = 0;
        #pragma unroll
        for (int s = 0; s < 16; s++) cnt += (u[s] >= Um) ? 1 : 0;
        #pragma unroll
        for (int o = 16; o; o >>= 1) cnt += __shfl_xor_sync(0xffffffffu, cnt, o);
        if (cnt >= k) lof = midf; else hif = midf;
        it++;
    }
    float Tf = lof;
    unsigned Uhi = f2ord(Tf + DELTA);
    unsigned Ulo = f2ord(Tf - DELTA);

    // ---- margin partition (ordered-uint compares) ----
    int nhi = 0, nbo = 0;
    #pragma unroll
    for (int s = 0; s < 16; s++) {
        nhi += (u[s] > Uhi) ? 1 : 0;
        nbo += (u[s] >= Ulo && u[s] <= Uhi) ? 1 : 0;
    }
    #pragma unroll
    for (int o = 16; o; o >>= 1) {
        nhi += __shfl_xor_sync(0xffffffffu, nhi, o);
        nbo += __shfl_xor_sync(0xffffffffu, nbo, o);
    }
    int r = k - nhi;

    bool win[16];
    if (nbo == r || nbo > 32) {
        unsigned Tcmp = (nbo > 32) ? f2ord(Tf) : Ulo;
        #pragma unroll
        for (int s = 0; s < 16; s++) win[s] = (u[s] >= Tcmp);
    } else {
        // ---- rare path: exact fp32 recompute of borderline elements ----
        if (lane < 16) s_bm[w][lane] = 0u;
        int base = 0;
        #pragma unroll
        for (int i = 0; i < 4; i++) {
            #pragma unroll
            for (int q = 0; q < 4; q++) {
                int s = i * 4 + q;
                bool isb = (u[s] >= Ulo && u[s] <= Uhi);
                unsigned m = __ballot_sync(0xffffffffu, isb);
                if (isb) {
                    int pos = base + __popc(m & ((1u << lane) - 1u));
                    s_bi[w][pos] = i * 128 + lane * 4 + q;
                }
                base += __popc(m);
            }
        }
        __syncwarp();
        int mcnt = base;
        const float* xi = x_in  + (size_t)b * DD;
        const float* xc = x_ctx + (size_t)b * DD;
        for (int e = 0; e < mcnt; e++) {
            int ncol = s_bi[w][e];
            const float* wf = Wff  + ((size_t)c * DD) * NN + ncol;
            const float* wc = Wctx + ((size_t)c * DD) * NN + ncol;
            float aff = 0.f, act2 = 0.f;
            #pragma unroll
            for (int t = 0; t < 8; t++) {
                int d = lane + t * 32;
                aff  = fmaf(xi[d], wf[(size_t)d * NN], aff);
                act2 = fmaf(xc[d], wc[(size_t)d * NN], act2);
            }
            #pragma unroll
            for (int o = 16; o; o >>= 1) {
                aff  += __shfl_xor_sync(0xffffffffu, aff,  o);
                act2 += __shfl_xor_sync(0xffffffffu, act2, o);
            }
            if (lane == 0)
                s_be[w][e] = aff + act2 * 0.3f + bias[(size_t)c * NN + ncol]
                           + g_boost[(size_t)c * NN + ncol];
            __syncwarp();
        }
        if (lane < mcnt) {
            float v = s_be[w][lane];
            int g = 0;
            for (int j = 0; j < mcnt; j++) g += (s_be[w][j] > v) ? 1 : 0;
            if (g < r) {
                int col = s_bi[w][lane];
                atomicOr(&s_bm[w][col >> 5], 1u << (col & 31));
            }
        }
        __syncwarp();
        #pragma unroll
        for (int i = 0; i < 4; i++) {
            #pragma unroll
            for (int q = 0; q < 4; q++) {
                int s = i * 4 + q;
                int col = i * 128 + lane * 4 + q;
                bool inbm = (s_bm[w][col >> 5] >> (col & 31)) & 1u;
                win[s] = (u[s] > Uhi) || inbm;
            }
        }
    }

    // ---- normalization ----
    float lsum = 0.f;
    #pragma unroll
    for (int s = 0; s < 16; s++) {
        float rl = fmaxf(f[s], 0.f);
        lsum += win[s] ? rl : 0.f;
    }
    #pragma unroll
    for (int o = 16; o; o >>= 1) lsum += __shfl_xor_sync(0xffffffffu, lsum, o);
    float scale = (float)k / (lsum + 1e-8f);

    // ---- write act + compact nonzero winners ----
    float4* orow = reinterpret_cast<float4*>(act + (size_t)row * NN);
    int cnt_total = 0;
    #pragma unroll
    for (int i = 0; i < 4; i++) {
        float ov[4];
        #pragma unroll
        for (int q = 0; q < 4; q++) {
            int s = i * 4 + q;
            float rl  = fmaxf(f[s], 0.f);
            float val = win[s] ? rl * scale : 0.f;
            ov[q] = val;
            bool put = win[s] && (rl > 0.f);
            unsigned m = __ballot_sync(0xffffffffu, put);
            if (put) {
                int pos = cnt_total + __popc(m & ((1u << lane) - 1u));
                if (pos < 64) {
                    s_ii[w][pos] = i * 128 + lane * 4 + q;
                    s_vv[w][pos] = val;
                }
            }
            cnt_total += __popc(m);
        }
        orow[i * 32 + lane] = make_float4(ov[0], ov[1], ov[2], ov[3]);
    }
    if (cnt_total > 64) cnt_total = 64;
    __syncwarp();

    // ---- sparse prediction + error ----
    const float* WpC = Wp + (size_t)c * NN * DD;
    float4 acc0 = make_float4(0.f, 0.f, 0.f, 0.f);
    float4 acc1 = make_float4(0.f, 0.f, 0.f, 0.f);
    for (int j = 0; j < cnt_total; j++) {
        float vj = s_vv[w][j];
        const float4* wr = reinterpret_cast<const float4*>(WpC + (size_t)s_ii[w][j] * DD);
        float4 w0 = wr[lane];
        float4 w1 = wr[lane + 32];
        acc0.x = fmaf(vj, w0.x, acc0.x); acc0.y = fmaf(vj, w0.y, acc0.y);
        acc0.z = fmaf(vj, w0.z, acc0.z); acc0.w = fmaf(vj, w0.w, acc0.w);
        acc1.x = fmaf(vj, w1.x, acc1.x); acc1.y = fmaf(vj, w1.y, acc1.y);
        acc1.z = fmaf(vj, w1.z, acc1.z); acc1.w = fmaf(vj, w1.w, acc1.w);
    }

    const float4* xr = reinterpret_cast<const float4*>(x_in + (size_t)b * DD);
    float4 x0 = xr[lane], x1 = xr[lane + 32];
    float4* prow = reinterpret_cast<float4*>(pred + (size_t)row * DD);
    float4* erow = reinterpret_cast<float4*>(err  + (size_t)row * DD);
    prow[lane]      = acc0;
    prow[lane + 32] = acc1;
    erow[lane]      = make_float4(x0.x - acc0.x, x0.y - acc0.y, x0.z - acc0.z, x0.w - acc0.w);
    erow[lane + 32] = make_float4(x1.x - acc1.x, x1.y - acc1.y, x1.z - acc1.z, x1.w - acc1.w);
}

// ---------------------------------------------------------------------------
extern "C" void kernel_launch(void* const* d_in, const int* in_sizes, int n_in,
                              void* d_out, int out_size)
{
    const float* x_in  = (const float*)d_in[0];
    const float* x_ctx = (const float*)d_in[1];
    const float* Wff   = (const float*)d_in[2];
    const float* Wctx  = (const float*)d_in[3];
    const float* Wpred = (const float*)d_in[4];
    const float* bias  = (const float*)d_in[5];
    const float* avg   = (const float*)d_in[6];
    const int*   kptr  = (const int*)d_in[7];

    float* act  = (float*)d_out;                              // [B,C,N]
    float* pred = act  + (size_t)BB * CC * NN;                // [B,C,D]
    float* err  = pred + (size_t)BB * CC * DD;                // [B,C,D]

    cudaFuncSetAttribute(drive_gemm,
                         cudaFuncAttributeMaxDynamicSharedMemorySize, DRIVE_SMEM);

    boost_kernel<<<(CC * NN + 255) / 256, 256>>>(avg);
    prep_A<<<(BB * K2 + 255) / 256, 256>>>(x_in, x_ctx);

    dim3 g1(NN / 128, BB / 128, CC);
    drive_gemm<<<g1, 256, DRIVE_SMEM>>>(Wff, Wctx, bias, act);

    topk_pred<<<BB * CC / 8, 256>>>(kptr, x_in, x_ctx, Wff, Wctx, bias,
                                    Wpred, act, pred, err);
}

// round 13
// speedup vs baseline: 1.3016x; 1.3016x over previous
#include <cuda_runtime.h>
#include <math.h>

#define BB 1024
#define CC 64
#define DD 256
#define NN 512
#define K2 (2*DD)
#define DELTA 1e-4f

__device__ float g_boost[CC*NN];

// ---------------------------------------------------------------------------
// Kernel 0: boost[c,n] = log1p(0.05/(avg+1e-6))   (batch-independent)
// ---------------------------------------------------------------------------
__global__ void boost_kernel(const float* __restrict__ avg) {
    int i = blockIdx.x * blockDim.x + threadIdx.x;
    if (i < CC * NN) g_boost[i] = log1pf(0.05f / (avg[i] + 1e-6f));
}

// ---- tf32 split ----
__device__ __forceinline__ float2 split1(float f) {
    unsigned h;
    asm("cvt.rna.tf32.f32 %0, %1;" : "=r"(h) : "f"(f));
    float hf = __uint_as_float(h);
    return make_float2(hf, f - hf);
}
__device__ __forceinline__ void mma_tf32(
    float& c0, float& c1, float& c2, float& c3,
    unsigned a0, unsigned a1, unsigned a2, unsigned a3,
    unsigned b0, unsigned b1)
{
    asm("mma.sync.aligned.m16n8k8.row.col.f32.tf32.tf32.f32 "
        "{%0,%1,%2,%3},{%4,%5,%6,%7},{%8,%9},{%0,%1,%2,%3};"
        : "+f"(c0), "+f"(c1), "+f"(c2), "+f"(c3)
        : "r"(a0), "r"(a1), "r"(a2), "r"(a3), "r"(b0), "r"(b1));
}

// ---------------------------------------------------------------------------
// Kernel 1: drive GEMM via 3xTF32 — EXACT round-7 kernel (measured best 527us).
// ---------------------------------------------------------------------------
__global__ __launch_bounds__(256) void drive_gemm(
    const float* __restrict__ x_in, const float* __restrict__ x_ctx,
    const float* __restrict__ Wff,  const float* __restrict__ Wctx,
    const float* __restrict__ bias, float* __restrict__ act)
{
    const int BM = 128, BN = 128, BK = 16, LD = 136;
    __shared__ float As[2][BK][LD];
    __shared__ float Bs[2][BK][LD];

    int c  = blockIdx.z;
    int m0 = blockIdx.y * BM;
    int n0 = blockIdx.x * BN;
    int tid  = threadIdx.x;
    int warp = tid >> 5, lane = tid & 31;
    int wm = (warp & 1) * 64;
    int wn = (warp >> 1) * 32;
    int ar = lane >> 2;
    int ac = lane & 3;

    float acc[16][4];
    #pragma unroll
    for (int i = 0; i < 16; i++)
        #pragma unroll
        for (int j = 0; j < 4; j++) acc[i][j] = 0.f;

    const float* WffC  = Wff  + (size_t)c * DD * NN;
    const float* WctxC = Wctx + (size_t)c * DD * NN;

    {
        #pragma unroll
        for (int i = 0; i < 2; i++) {
            int t = tid + i * 256;
            int m = t >> 2, kq = (t & 3) << 2;
            float4 v = *reinterpret_cast<const float4*>(x_in + (size_t)(m0 + m) * DD + kq);
            As[0][kq+0][m] = v.x; As[0][kq+1][m] = v.y;
            As[0][kq+2][m] = v.z; As[0][kq+3][m] = v.w;
        }
        #pragma unroll
        for (int i = 0; i < 2; i++) {
            int t = tid + i * 256;
            int kk = t >> 5, nq = (t & 31) << 2;
            *reinterpret_cast<float4*>(&Bs[0][kk][nq]) =
                *reinterpret_cast<const float4*>(WffC + (size_t)kk * NN + n0 + nq);
        }
    }
    __syncthreads();

    int cur = 0;
    for (int kt = 0; kt < K2 / BK; kt++) {
        float4 pa[2], pb[2];
        float  nscale = 1.0f;
        bool   has_next = (kt + 1 < K2 / BK);
        if (has_next) {
            int k0 = (kt + 1) * BK;
            const float* asrc = (k0 < DD) ? (x_in + k0) : (x_ctx + (k0 - DD));
            nscale = (k0 < DD) ? 1.0f : 0.3f;
            #pragma unroll
            for (int i = 0; i < 2; i++) {
                int t = tid + i * 256;
                int m = t >> 2, kq = (t & 3) << 2;
                pa[i] = *reinterpret_cast<const float4*>(asrc + (size_t)(m0 + m) * DD + kq);
            }
            const float* wsrc = (k0 < DD) ? (WffC + (size_t)k0 * NN)
                                          : (WctxC + (size_t)(k0 - DD) * NN);
            #pragma unroll
            for (int i = 0; i < 2; i++) {
                int t = tid + i * 256;
                int kk = t >> 5, nq = (t & 31) << 2;
                pb[i] = *reinterpret_cast<const float4*>(wsrc + (size_t)kk * NN + n0 + nq);
            }
        }

        #pragma unroll
        for (int kh = 0; kh < 2; kh++) {
            int kk0 = kh * 8;
            unsigned bh[8], bl[8];
            #pragma unroll
            for (int sn = 0; sn < 4; sn++) {
                float b0 = Bs[cur][kk0 + ac    ][wn + sn * 8 + ar];
                float b1 = Bs[cur][kk0 + ac + 4][wn + sn * 8 + ar];
                float2 s0 = split1(b0), s1 = split1(b1);
                bh[sn*2+0] = __float_as_uint(s0.x); bl[sn*2+0] = __float_as_uint(s0.y);
                bh[sn*2+1] = __float_as_uint(s1.x); bl[sn*2+1] = __float_as_uint(s1.y);
            }
            #pragma unroll
            for (int sm = 0; sm < 4; sm++) {
                int mb = wm + sm * 16;
                float a0 = As[cur][kk0 + ac    ][mb + ar];
                float a1 = As[cur][kk0 + ac    ][mb + ar + 8];
                float a2 = As[cur][kk0 + ac + 4][mb + ar];
                float a3 = As[cur][kk0 + ac + 4][mb + ar + 8];
                float2 sa0 = split1(a0), sa1 = split1(a1);
                float2 sa2 = split1(a2), sa3 = split1(a3);
                unsigned ah0 = __float_as_uint(sa0.x), al0 = __float_as_uint(sa0.y);
                unsigned ah1 = __float_as_uint(sa1.x), al1 = __float_as_uint(sa1.y);
                unsigned ah2 = __float_as_uint(sa2.x), al2 = __float_as_uint(sa2.y);
                unsigned ah3 = __float_as_uint(sa3.x), al3 = __float_as_uint(sa3.y);
                #pragma unroll
                for (int sn = 0; sn < 4; sn++) {
                    float* cp = acc[sm * 4 + sn];
                    mma_tf32(cp[0], cp[1], cp[2], cp[3],
                             ah0, ah1, ah2, ah3, bh[sn*2], bh[sn*2+1]);
                    mma_tf32(cp[0], cp[1], cp[2], cp[3],
                             ah0, ah1, ah2, ah3, bl[sn*2], bl[sn*2+1]);
                    mma_tf32(cp[0], cp[1], cp[2], cp[3],
                             al0, al1, al2, al3, bh[sn*2], bh[sn*2+1]);
                }
            }
        }

        if (has_next) {
            int nxt = cur ^ 1;
            #pragma unroll
            for (int i = 0; i < 2; i++) {
                int t = tid + i * 256;
                int m = t >> 2, kq = (t & 3) << 2;
                As[nxt][kq+0][m] = pa[i].x * nscale;
                As[nxt][kq+1][m] = pa[i].y * nscale;
                As[nxt][kq+2][m] = pa[i].z * nscale;
                As[nxt][kq+3][m] = pa[i].w * nscale;
            }
            #pragma unroll
            for (int i = 0; i < 2; i++) {
                int t = tid + i * 256;
                int kk = t >> 5, nq = (t & 31) << 2;
                *reinterpret_cast<float4*>(&Bs[nxt][kk][nq]) = pb[i];
            }
            __syncthreads();
            cur = nxt;
        }
    }

    const float* bc = bias + (size_t)c * NN;
    #pragma unroll
    for (int sm = 0; sm < 4; sm++) {
        #pragma unroll
        for (int sn = 0; sn < 4; sn++) {
            const float* cp = acc[sm * 4 + sn];
            int col = n0 + wn + sn * 8 + ac * 2;
            float bx = bc[col], by = bc[col + 1];
            int r0 = m0 + wm + sm * 16 + ar;
            float2 v0 = make_float2(cp[0] + bx, cp[1] + by);
            float2 v1 = make_float2(cp[2] + bx, cp[3] + by);
            *reinterpret_cast<float2*>(act + ((size_t)r0 * CC + c) * NN + col)       = v0;
            *reinterpret_cast<float2*>(act + ((size_t)(r0 + 8) * CC + c) * NN + col) = v1;
        }
    }
}

// ---------------------------------------------------------------------------
// Kernel 2: warp-per-row k-WTA — EXACT round-12 kernel (measured best 188us).
// ---------------------------------------------------------------------------
__device__ __forceinline__ unsigned f2ord(float f) {
    unsigned u = __float_as_uint(f);
    return (u & 0x80000000u) ? ~u : (u | 0x80000000u);
}
__device__ __forceinline__ float ord2f(unsigned u) {
    unsigned v = (u & 0x80000000u) ? (u & 0x7FFFFFFFu) : ~u;
    return __uint_as_float(v);
}

__global__ __launch_bounds__(256, 4) void topk_pred(
    const int* __restrict__ kptr, const float* __restrict__ x_in,
    const float* __restrict__ x_ctx,
    const float* __restrict__ Wff, const float* __restrict__ Wctx,
    const float* __restrict__ bias,
    const float* __restrict__ Wp,
    float* __restrict__ act, float* __restrict__ pred, float* __restrict__ err)
{
    int lane = threadIdx.x & 31;
    int w    = threadIdx.x >> 5;
    int row  = blockIdx.x * 8 + w;          // b*C + c
    int c = row & (CC - 1);
    int b = row >> 6;

    __shared__ float s_vv[8][64];
    __shared__ int   s_ii[8][64];
    __shared__ int   s_bi[8][32];
    __shared__ float s_be[8][32];
    __shared__ unsigned s_bm[8][16];

    const float4* arow = reinterpret_cast<const float4*>(act + (size_t)row * NN);
    const float4* brow = reinterpret_cast<const float4*>(g_boost + (size_t)c * NN);

    float    f[16];
    unsigned u[16];
    #pragma unroll
    for (int i = 0; i < 4; i++) {
        float4 a  = arow[i * 32 + lane];
        float4 bo = brow[i * 32 + lane];
        f[i*4+0] = a.x; f[i*4+1] = a.y; f[i*4+2] = a.z; f[i*4+3] = a.w;
        u[i*4+0] = f2ord(a.x + bo.x);
        u[i*4+1] = f2ord(a.y + bo.y);
        u[i*4+2] = f2ord(a.z + bo.z);
        u[i*4+3] = f2ord(a.w + bo.w);
    }

    int k = *kptr;

    unsigned lmax = 0, lmin = 0xFFFFFFFFu;
    #pragma unroll
    for (int s = 0; s < 16; s++) { lmax = max(lmax, u[s]); lmin = min(lmin, u[s]); }
    unsigned mx = lmax, lb = lmax, gmn = lmin;
    #pragma unroll
    for (int o = 16; o; o >>= 1) {
        mx  = max(mx,  __shfl_xor_sync(0xffffffffu, mx,  o));
        lb  = min(lb,  __shfl_xor_sync(0xffffffffu, lb,  o));
        gmn = min(gmn, __shfl_xor_sync(0xffffffffu, gmn, o));
    }
    if (k > 32) lb = gmn;

    float lof = ord2f(lb);
    float hif = ord2f(mx + 1u);
    int it = 0;
    while (hif - lof > 2.5e-5f && it < 40) {
        float midf = 0.5f * (lof + hif);
        unsigned Um = f2ord(midf);
        int cnt = 0;
        #pragma unroll
        for (int s = 0; s < 16; s++) cnt += (u[s] >= Um) ? 1 : 0;
        #pragma unroll
        for (int o = 16; o; o >>= 1) cnt += __shfl_xor_sync(0xffffffffu, cnt, o);
        if (cnt >= k) lof = midf; else hif = midf;
        it++;
    }
    float Tf = lof;
    unsigned Uhi = f2ord(Tf + DELTA);
    unsigned Ulo = f2ord(Tf - DELTA);

    int nhi = 0, nbo = 0;
    #pragma unroll
    for (int s = 0; s < 16; s++) {
        nhi += (u[s] > Uhi) ? 1 : 0;
        nbo += (u[s] >= Ulo && u[s] <= Uhi) ? 1 : 0;
    }
    #pragma unroll
    for (int o = 16; o; o >>= 1) {
        nhi += __shfl_xor_sync(0xffffffffu, nhi, o);
        nbo += __shfl_xor_sync(0xffffffffu, nbo, o);
    }
    int r = k - nhi;

    bool win[16];
    if (nbo == r || nbo > 32) {
        unsigned Tcmp = (nbo > 32) ? f2ord(Tf) : Ulo;
        #pragma unroll
        for (int s = 0; s < 16; s++) win[s] = (u[s] >= Tcmp);
    } else {
        if (lane < 16) s_bm[w][lane] = 0u;
        int base = 0;
        #pragma unroll
        for (int i = 0; i < 4; i++) {
            #pragma unroll
            for (int q = 0; q < 4; q++) {
                int s = i * 4 + q;
                bool isb = (u[s] >= Ulo && u[s] <= Uhi);
                unsigned m = __ballot_sync(0xffffffffu, isb);
                if (isb) {
                    int pos = base + __popc(m & ((1u << lane) - 1u));
                    s_bi[w][pos] = i * 128 + lane * 4 + q;
                }
                base += __popc(m);
            }
        }
        __syncwarp();
        int mcnt = base;
        const float* xi = x_in  + (size_t)b * DD;
        const float* xc = x_ctx + (size_t)b * DD;
        for (int e = 0; e < mcnt; e++) {
            int ncol = s_bi[w][e];
            const float* wf = Wff  + ((size_t)c * DD) * NN + ncol;
            const float* wc = Wctx + ((size_t)c * DD) * NN + ncol;
            float aff = 0.f, act2 = 0.f;
            #pragma unroll
            for (int t = 0; t < 8; t++) {
                int d = lane + t * 32;
                aff  = fmaf(xi[d], wf[(size_t)d * NN], aff);
                act2 = fmaf(xc[d], wc[(size_t)d * NN], act2);
            }
            #pragma unroll
            for (int o = 16; o; o >>= 1) {
                aff  += __shfl_xor_sync(0xffffffffu, aff,  o);
                act2 += __shfl_xor_sync(0xffffffffu, act2, o);
            }
            if (lane == 0)
                s_be[w][e] = aff + act2 * 0.3f + bias[(size_t)c * NN + ncol]
                           + g_boost[(size_t)c * NN + ncol];
            __syncwarp();
        }
        if (lane < mcnt) {
            float v = s_be[w][lane];
            int g = 0;
            for (int j = 0; j < mcnt; j++) g += (s_be[w][j] > v) ? 1 : 0;
            if (g < r) {
                int col = s_bi[w][lane];
                atomicOr(&s_bm[w][col >> 5], 1u << (col & 31));
            }
        }
        __syncwarp();
        #pragma unroll
        for (int i = 0; i < 4; i++) {
            #pragma unroll
            for (int q = 0; q < 4; q++) {
                int s = i * 4 + q;
                int col = i * 128 + lane * 4 + q;
                bool inbm = (s_bm[w][col >> 5] >> (col & 31)) & 1u;
                win[s] = (u[s] > Uhi) || inbm;
            }
        }
    }

    float lsum = 0.f;
    #pragma unroll
    for (int s = 0; s < 16; s++) {
        float rl = fmaxf(f[s], 0.f);
        lsum += win[s] ? rl : 0.f;
    }
    #pragma unroll
    for (int o = 16; o; o >>= 1) lsum += __shfl_xor_sync(0xffffffffu, lsum, o);
    float scale = (float)k / (lsum + 1e-8f);

    float4* orow = reinterpret_cast<float4*>(act + (size_t)row * NN);
    int cnt_total = 0;
    #pragma unroll
    for (int i = 0; i < 4; i++) {
        float ov[4];
        #pragma unroll
        for (int q = 0; q < 4; q++) {
            int s = i * 4 + q;
            float rl  = fmaxf(f[s], 0.f);
            float val = win[s] ? rl * scale : 0.f;
            ov[q] = val;
            bool put = win[s] && (rl > 0.f);
            unsigned m = __ballot_sync(0xffffffffu, put);
            if (put) {
                int pos = cnt_total + __popc(m & ((1u << lane) - 1u));
                if (pos < 64) {
                    s_ii[w][pos] = i * 128 + lane * 4 + q;
                    s_vv[w][pos] = val;
                }
            }
            cnt_total += __popc(m);
        }
        orow[i * 32 + lane] = make_float4(ov[0], ov[1], ov[2], ov[3]);
    }
    if (cnt_total > 64) cnt_total = 64;
    __syncwarp();

    const float* WpC = Wp + (size_t)c * NN * DD;
    float4 acc0 = make_float4(0.f, 0.f, 0.f, 0.f);
    float4 acc1 = make_float4(0.f, 0.f, 0.f, 0.f);
    for (int j = 0; j < cnt_total; j++) {
        float vj = s_vv[w][j];
        const float4* wr = reinterpret_cast<const float4*>(WpC + (size_t)s_ii[w][j] * DD);
        float4 w0 = wr[lane];
        float4 w1 = wr[lane + 32];
        acc0.x = fmaf(vj, w0.x, acc0.x); acc0.y = fmaf(vj, w0.y, acc0.y);
        acc0.z = fmaf(vj, w0.z, acc0.z); acc0.w = fmaf(vj, w0.w, acc0.w);
        acc1.x = fmaf(vj, w1.x, acc1.x); acc1.y = fmaf(vj, w1.y, acc1.y);
        acc1.z = fmaf(vj, w1.z, acc1.z); acc1.w = fmaf(vj, w1.w, acc1.w);
    }

    const float4* xr = reinterpret_cast<const float4*>(x_in + (size_t)b * DD);
    float4 x0 = xr[lane], x1 = xr[lane + 32];
    float4* prow = reinterpret_cast<float4*>(pred + (size_t)row * DD);
    float4* erow = reinterpret_cast<float4*>(err  + (size_t)row * DD);
    prow[lane]      = acc0;
    prow[lane + 32] = acc1;
    erow[lane]      = make_float4(x0.x - acc0.x, x0.y - acc0.y, x0.z - acc0.z, x0.w - acc0.w);
    erow[lane + 32] = make_float4(x1.x - acc1.x, x1.y - acc1.y, x1.z - acc1.z, x1.w - acc1.w);
}

// ---------------------------------------------------------------------------
extern "C" void kernel_launch(void* const* d_in, const int* in_sizes, int n_in,
                              void* d_out, int out_size)
{
    const float* x_in  = (const float*)d_in[0];
    const float* x_ctx = (const float*)d_in[1];
    const float* Wff   = (const float*)d_in[2];
    const float* Wctx  = (const float*)d_in[3];
    const float* Wpred = (const float*)d_in[4];
    const float* bias  = (const float*)d_in[5];
    const float* avg   = (const float*)d_in[6];
    const int*   kptr  = (const int*)d_in[7];

    float* act  = (float*)d_out;                              // [B,C,N]
    float* pred = act  + (size_t)BB * CC * NN;                // [B,C,D]
    float* err  = pred + (size_t)BB * CC * DD;                // [B,C,D]

    boost_kernel<<<(CC * NN + 255) / 256, 256>>>(avg);

    dim3 g1(NN / 128, BB / 128, CC);
    drive_gemm<<<g1, 256>>>(x_in, x_ctx, Wff, Wctx, bias, act);

    topk_pred<<<BB * CC / 8, 256>>>(kptr, x_in, x_ctx, Wff, Wctx, bias,
                                    Wpred, act, pred, err);
}

// round 14
// speedup vs baseline: 1.6032x; 1.2317x over previous
#include <cuda_runtime.h>
#include <cuda_bf16.h>
#include <math.h>

#define BB 1024
#define CC 64
#define DD 256
#define NN 512
#define K2 (2*DD)
#define DELTA 4e-4f

__device__ float g_boost[CC*NN];

// ---------------------------------------------------------------------------
// Kernel 0: boost[c,n] = log1p(0.05/(avg+1e-6))   (batch-independent)
// ---------------------------------------------------------------------------
__global__ void boost_kernel(const float* __restrict__ avg) {
    int i = blockIdx.x * blockDim.x + threadIdx.x;
    if (i < CC * NN) g_boost[i] = log1pf(0.05f / (avg[i] + 1e-6f));
}

// ---- bf16 hi/lo split of a k-adjacent pair -> packed {hi2, lo2} ----
__device__ __forceinline__ uint2 bsplit2(float x, float y) {
    __nv_bfloat162 h = __floats2bfloat162_rn(x, y);
    float rx = x - __bfloat162float(h.x);
    float ry = y - __bfloat162float(h.y);
    __nv_bfloat162 l = __floats2bfloat162_rn(rx, ry);
    uint2 r;
    r.x = *reinterpret_cast<unsigned*>(&h);
    r.y = *reinterpret_cast<unsigned*>(&l);
    return r;
}

__device__ __forceinline__ void mma_bf16(
    float* cp, unsigned a0, unsigned a1, unsigned a2, unsigned a3,
    unsigned b0, unsigned b1)
{
    asm("mma.sync.aligned.m16n8k16.row.col.f32.bf16.bf16.f32 "
        "{%0,%1,%2,%3},{%4,%5,%6,%7},{%8,%9},{%0,%1,%2,%3};"
        : "+f"(cp[0]), "+f"(cp[1]), "+f"(cp[2]), "+f"(cp[3])
        : "r"(a0), "r"(a1), "r"(a2), "r"(a3), "r"(b0), "r"(b1));
}

// ---------------------------------------------------------------------------
// Kernel 1: drive GEMM via 3xBF16 (m16n8k16). Round-7 skeleton: 128x128 tile,
// BK=16, double-buffered, one sync per k-tile. Operands pre-split+packed into
// uint2{hi2,lo2} smem planes [k2][x] stride 132 (conflict-free LDS.64 frags).
// Inner loop: pure LDS.64 + 48 MMA per warp per tile.
// ---------------------------------------------------------------------------
#define LD2 132

__global__ __launch_bounds__(256) void drive_gemm(
    const float* __restrict__ x_in, const float* __restrict__ x_ctx,
    const float* __restrict__ Wff,  const float* __restrict__ Wctx,
    const float* __restrict__ bias, float* __restrict__ act)
{
    __shared__ uint2 A2s[2][8][LD2];   // [buf][k2][m]  {hi2, lo2}
    __shared__ uint2 B2s[2][8][LD2];   // [buf][k2][n]

    int c  = blockIdx.z;
    int m0 = blockIdx.y * 128;
    int n0 = blockIdx.x * 128;
    int tid  = threadIdx.x;
    int warp = tid >> 5, lane = tid & 31;
    int wm = (warp & 1) * 64;
    int wn = (warp >> 1) * 32;
    int ar = lane >> 2;      // groupID
    int ac = lane & 3;       // threadID-in-group

    float acc[16][4];
    #pragma unroll
    for (int i = 0; i < 16; i++)
        #pragma unroll
        for (int j = 0; j < 4; j++) acc[i][j] = 0.f;

    const float* WffC  = Wff  + (size_t)c * DD * NN;
    const float* WctxC = Wctx + (size_t)c * DD * NN;

    // B loader coords (1 slot/thread): two k-rows, 4 n
    int bk2 = tid >> 5, bnq = (tid & 31) << 2;

    // ---- preload k-tile 0 (ff half, nscale=1) ----
    {
        #pragma unroll
        for (int i = 0; i < 2; i++) {
            int t = tid + i * 256;
            int m = t >> 2, kq = (t & 3) << 2;
            float4 v = *reinterpret_cast<const float4*>(x_in + (size_t)(m0 + m) * DD + kq);
            A2s[0][(kq >> 1)    ][m] = bsplit2(v.x, v.y);
            A2s[0][(kq >> 1) + 1][m] = bsplit2(v.z, v.w);
        }
        const float* wp = WffC + (size_t)(2 * bk2) * NN + n0 + bnq;
        float4 r0 = *reinterpret_cast<const float4*>(wp);
        float4 r1 = *reinterpret_cast<const float4*>(wp + NN);
        B2s[0][bk2][bnq + 0] = bsplit2(r0.x, r1.x);
        B2s[0][bk2][bnq + 1] = bsplit2(r0.y, r1.y);
        B2s[0][bk2][bnq + 2] = bsplit2(r0.z, r1.z);
        B2s[0][bk2][bnq + 3] = bsplit2(r0.w, r1.w);
    }
    __syncthreads();

    int cur = 0;
    for (int kt = 0; kt < K2 / 16; kt++) {
        float4 pa[2], pb0, pb1;
        float  nscale = 1.0f;
        bool   has_next = (kt + 1 < K2 / 16);
        if (has_next) {
            int k0 = (kt + 1) * 16;
            const float* asrc = (k0 < DD) ? (x_in + k0) : (x_ctx + (k0 - DD));
            nscale = (k0 < DD) ? 1.0f : 0.3f;
            #pragma unroll
            for (int i = 0; i < 2; i++) {
                int t = tid + i * 256;
                int m = t >> 2, kq = (t & 3) << 2;
                pa[i] = *reinterpret_cast<const float4*>(asrc + (size_t)(m0 + m) * DD + kq);
            }
            const float* wsrc = (k0 < DD) ? (WffC + (size_t)k0 * NN)
                                          : (WctxC + (size_t)(k0 - DD) * NN);
            const float* wp = wsrc + (size_t)(2 * bk2) * NN + n0 + bnq;
            pb0 = *reinterpret_cast<const float4*>(wp);
            pb1 = *reinterpret_cast<const float4*>(wp + NN);
        }

        // ---- compute: one k16 step ----
        uint2 bf0[4], bf1[4];
        #pragma unroll
        for (int sn = 0; sn < 4; sn++) {
            int col = wn + sn * 8 + ar;
            bf0[sn] = B2s[cur][ac    ][col];
            bf1[sn] = B2s[cur][ac + 4][col];
        }
        #pragma unroll
        for (int sm = 0; sm < 4; sm++) {
            int mb = wm + sm * 16;
            uint2 A0 = A2s[cur][ac    ][mb + ar];
            uint2 A1 = A2s[cur][ac    ][mb + ar + 8];
            uint2 A2f = A2s[cur][ac + 4][mb + ar];
            uint2 A3 = A2s[cur][ac + 4][mb + ar + 8];
            #pragma unroll
            for (int sn = 0; sn < 4; sn++) {
                float* cp = acc[sm * 4 + sn];
                mma_bf16(cp, A0.x, A1.x, A2f.x, A3.x, bf0[sn].x, bf1[sn].x); // Ah*Bh
                mma_bf16(cp, A0.x, A1.x, A2f.x, A3.x, bf0[sn].y, bf1[sn].y); // Ah*Bl
                mma_bf16(cp, A0.y, A1.y, A2f.y, A3.y, bf0[sn].x, bf1[sn].x); // Al*Bh
            }
        }

        if (has_next) {
            int nxt = cur ^ 1;
            #pragma unroll
            for (int i = 0; i < 2; i++) {
                int t = tid + i * 256;
                int m = t >> 2, kq = (t & 3) << 2;
                A2s[nxt][(kq >> 1)    ][m] = bsplit2(pa[i].x * nscale, pa[i].y * nscale);
                A2s[nxt][(kq >> 1) + 1][m] = bsplit2(pa[i].z * nscale, pa[i].w * nscale);
            }
            B2s[nxt][bk2][bnq + 0] = bsplit2(pb0.x, pb1.x);
            B2s[nxt][bk2][bnq + 1] = bsplit2(pb0.y, pb1.y);
            B2s[nxt][bk2][bnq + 2] = bsplit2(pb0.z, pb1.z);
            B2s[nxt][bk2][bnq + 3] = bsplit2(pb0.w, pb1.w);
            __syncthreads();
            cur = nxt;
        }
    }

    // ---- epilogue: + bias, scatter (same C layout as m16n8k8) ----
    const float* bc = bias + (size_t)c * NN;
    #pragma unroll
    for (int sm = 0; sm < 4; sm++) {
        #pragma unroll
        for (int sn = 0; sn < 4; sn++) {
            const float* cp = acc[sm * 4 + sn];
            int col = n0 + wn + sn * 8 + ac * 2;
            float bx = bc[col], by = bc[col + 1];
            int r0 = m0 + wm + sm * 16 + ar;
            float2 v0 = make_float2(cp[0] + bx, cp[1] + by);
            float2 v1 = make_float2(cp[2] + bx, cp[3] + by);
            *reinterpret_cast<float2*>(act + ((size_t)r0 * CC + c) * NN + col)       = v0;
            *reinterpret_cast<float2*>(act + ((size_t)(r0 + 8) * CC + c) * NN + col) = v1;
        }
    }
}

// ---------------------------------------------------------------------------
// Kernel 2: warp-per-row k-WTA — round-12/13 kernel (188us), DELTA widened.
// ---------------------------------------------------------------------------
__device__ __forceinline__ unsigned f2ord(float f) {
    unsigned u = __float_as_uint(f);
    return (u & 0x80000000u) ? ~u : (u | 0x80000000u);
}
__device__ __forceinline__ float ord2f(unsigned u) {
    unsigned v = (u & 0x80000000u) ? (u & 0x7FFFFFFFu) : ~u;
    return __uint_as_float(v);
}

__global__ __launch_bounds__(256, 4) void topk_pred(
    const int* __restrict__ kptr, const float* __restrict__ x_in,
    const float* __restrict__ x_ctx,
    const float* __restrict__ Wff, const float* __restrict__ Wctx,
    const float* __restrict__ bias,
    const float* __restrict__ Wp,
    float* __restrict__ act, float* __restrict__ pred, float* __restrict__ err)
{
    int lane = threadIdx.x & 31;
    int w    = threadIdx.x >> 5;
    int row  = blockIdx.x * 8 + w;          // b*C + c
    int c = row & (CC - 1);
    int b = row >> 6;

    __shared__ float s_vv[8][64];
    __shared__ int   s_ii[8][64];
    __shared__ int   s_bi[8][32];
    __shared__ float s_be[8][32];
    __shared__ unsigned s_bm[8][16];

    const float4* arow = reinterpret_cast<const float4*>(act + (size_t)row * NN);
    const float4* brow = reinterpret_cast<const float4*>(g_boost + (size_t)c * NN);

    float    f[16];
    unsigned u[16];
    #pragma unroll
    for (int i = 0; i < 4; i++) {
        float4 a  = arow[i * 32 + lane];
        float4 bo = brow[i * 32 + lane];
        f[i*4+0] = a.x; f[i*4+1] = a.y; f[i*4+2] = a.z; f[i*4+3] = a.w;
        u[i*4+0] = f2ord(a.x + bo.x);
        u[i*4+1] = f2ord(a.y + bo.y);
        u[i*4+2] = f2ord(a.z + bo.z);
        u[i*4+3] = f2ord(a.w + bo.w);
    }

    int k = *kptr;

    unsigned lmax = 0, lmin = 0xFFFFFFFFu;
    #pragma unroll
    for (int s = 0; s < 16; s++) { lmax = max(lmax, u[s]); lmin = min(lmin, u[s]); }
    unsigned mx = lmax, lb = lmax, gmn = lmin;
    #pragma unroll
    for (int o = 16; o; o >>= 1) {
        mx  = max(mx,  __shfl_xor_sync(0xffffffffu, mx,  o));
        lb  = min(lb,  __shfl_xor_sync(0xffffffffu, lb,  o));
        gmn = min(gmn, __shfl_xor_sync(0xffffffffu, gmn, o));
    }
    if (k > 32) lb = gmn;

    float lof = ord2f(lb);
    float hif = ord2f(mx + 1u);
    int it = 0;
    while (hif - lof > 2.5e-5f && it < 40) {
        float midf = 0.5f * (lof + hif);
        unsigned Um = f2ord(midf);
        int cnt = 0;
        #pragma unroll
        for (int s = 0; s < 16; s++) cnt += (u[s] >= Um) ? 1 : 0;
        #pragma unroll
        for (int o = 16; o; o >>= 1) cnt += __shfl_xor_sync(0xffffffffu, cnt, o);
        if (cnt >= k) lof = midf; else hif = midf;
        it++;
    }
    float Tf = lof;
    unsigned Uhi = f2ord(Tf + DELTA);
    unsigned Ulo = f2ord(Tf - DELTA);

    int nhi = 0, nbo = 0;
    #pragma unroll
    for (int s = 0; s < 16; s++) {
        nhi += (u[s] > Uhi) ? 1 : 0;
        nbo += (u[s] >= Ulo && u[s] <= Uhi) ? 1 : 0;
    }
    #pragma unroll
    for (int o = 16; o; o >>= 1) {
        nhi += __shfl_xor_sync(0xffffffffu, nhi, o);
        nbo += __shfl_xor_sync(0xffffffffu, nbo, o);
    }
    int r = k - nhi;

    bool win[16];
    if (nbo == r || nbo > 32) {
        unsigned Tcmp = (nbo > 32) ? f2ord(Tf) : Ulo;
        #pragma unroll
        for (int s = 0; s < 16; s++) win[s] = (u[s] >= Tcmp);
    } else {
        if (lane < 16) s_bm[w][lane] = 0u;
        int base = 0;
        #pragma unroll
        for (int i = 0; i < 4; i++) {
            #pragma unroll
            for (int q = 0; q < 4; q++) {
                int s = i * 4 + q;
                bool isb = (u[s] >= Ulo && u[s] <= Uhi);
                unsigned m = __ballot_sync(0xffffffffu, isb);
                if (isb) {
                    int pos = base + __popc(m & ((1u << lane) - 1u));
                    s_bi[w][pos] = i * 128 + lane * 4 + q;
                }
                base += __popc(m);
            }
        }
        __syncwarp();
        int mcnt = base;
        const float* xi = x_in  + (size_t)b * DD;
        const float* xc = x_ctx + (size_t)b * DD;
        for (int e = 0; e < mcnt; e++) {
            int ncol = s_bi[w][e];
            const float* wf = Wff  + ((size_t)c * DD) * NN + ncol;
            const float* wc = Wctx + ((size_t)c * DD) * NN + ncol;
            float aff = 0.f, act2 = 0.f;
            #pragma unroll
            for (int t = 0; t < 8; t++) {
                int d = lane + t * 32;
                aff  = fmaf(xi[d], wf[(size_t)d * NN], aff);
                act2 = fmaf(xc[d], wc[(size_t)d * NN], act2);
            }
            #pragma unroll
            for (int o = 16; o; o >>= 1) {
                aff  += __shfl_xor_sync(0xffffffffu, aff,  o);
                act2 += __shfl_xor_sync(0xffffffffu, act2, o);
            }
            if (lane == 0)
                s_be[w][e] = aff + act2 * 0.3f + bias[(size_t)c * NN + ncol]
                           + g_boost[(size_t)c * NN + ncol];
            __syncwarp();
        }
        if (lane < mcnt) {
            float v = s_be[w][lane];
            int g = 0;
            for (int j = 0; j < mcnt; j++) g += (s_be[w][j] > v) ? 1 : 0;
            if (g < r) {
                int col = s_bi[w][lane];
                atomicOr(&s_bm[w][col >> 5], 1u << (col & 31));
            }
        }
        __syncwarp();
        #pragma unroll
        for (int i = 0; i < 4; i++) {
            #pragma unroll
            for (int q = 0; q < 4; q++) {
                int s = i * 4 + q;
                int col = i * 128 + lane * 4 + q;
                bool inbm = (s_bm[w][col >> 5] >> (col & 31)) & 1u;
                win[s] = (u[s] > Uhi) || inbm;
            }
        }
    }

    float lsum = 0.f;
    #pragma unroll
    for (int s = 0; s < 16; s++) {
        float rl = fmaxf(f[s], 0.f);
        lsum += win[s] ? rl : 0.f;
    }
    #pragma unroll
    for (int o = 16; o; o >>= 1) lsum += __shfl_xor_sync(0xffffffffu, lsum, o);
    float scale = (float)k / (lsum + 1e-8f);

    float4* orow = reinterpret_cast<float4*>(act + (size_t)row * NN);
    int cnt_total = 0;
    #pragma unroll
    for (int i = 0; i < 4; i++) {
        float ov[4];
        #pragma unroll
        for (int q = 0; q < 4; q++) {
            int s = i * 4 + q;
            float rl  = fmaxf(f[s], 0.f);
            float val = win[s] ? rl * scale : 0.f;
            ov[q] = val;
            bool put = win[s] && (rl > 0.f);
            unsigned m = __ballot_sync(0xffffffffu, put);
            if (put) {
                int pos = cnt_total + __popc(m & ((1u << lane) - 1u));
                if (pos < 64) {
                    s_ii[w][pos] = i * 128 + lane * 4 + q;
                    s_vv[w][pos] = val;
                }
            }
            cnt_total += __popc(m);
        }
        orow[i * 32 + lane] = make_float4(ov[0], ov[1], ov[2], ov[3]);
    }
    if (cnt_total > 64) cnt_total = 64;
    __syncwarp();

    const float* WpC = Wp + (size_t)c * NN * DD;
    float4 acc0 = make_float4(0.f, 0.f, 0.f, 0.f);
    float4 acc1 = make_float4(0.f, 0.f, 0.f, 0.f);
    for (int j = 0; j < cnt_total; j++) {
        float vj = s_vv[w][j];
        const float4* wr = reinterpret_cast<const float4*>(WpC + (size_t)s_ii[w][j] * DD);
        float4 w0 = wr[lane];
        float4 w1 = wr[lane + 32];
        acc0.x = fmaf(vj, w0.x, acc0.x); acc0.y = fmaf(vj, w0.y, acc0.y);
        acc0.z = fmaf(vj, w0.z, acc0.z); acc0.w = fmaf(vj, w0.w, acc0.w);
        acc1.x = fmaf(vj, w1.x, acc1.x); acc1.y = fmaf(vj, w1.y, acc1.y);
        acc1.z = fmaf(vj, w1.z, acc1.z); acc1.w = fmaf(vj, w1.w, acc1.w);
    }

    const float4* xr = reinterpret_cast<const float4*>(x_in + (size_t)b * DD);
    float4 x0 = xr[lane], x1 = xr[lane + 32];
    float4* prow = reinterpret_cast<float4*>(pred + (size_t)row * DD);
    float4* erow = reinterpret_cast<float4*>(err  + (size_t)row * DD);
    prow[lane]      = acc0;
    prow[lane + 32] = acc1;
    erow[lane]      = make_float4(x0.x - acc0.x, x0.y - acc0.y, x0.z - acc0.z, x0.w - acc0.w);
    erow[lane + 32] = make_float4(x1.x - acc1.x, x1.y - acc1.y, x1.z - acc1.z, x1.w - acc1.w);
}

// ---------------------------------------------------------------------------
extern "C" void kernel_launch(void* const* d_in, const int* in_sizes, int n_in,
                              void* d_out, int out_size)
{
    const float* x_in  = (const float*)d_in[0];
    const float* x_ctx = (const float*)d_in[1];
    const float* Wff   = (const float*)d_in[2];
    const float* Wctx  = (const float*)d_in[3];
    const float* Wpred = (const float*)d_in[4];
    const float* bias  = (const float*)d_in[5];
    const float* avg   = (const float*)d_in[6];
    const int*   kptr  = (const int*)d_in[7];

    float* act  = (float*)d_out;                              // [B,C,N]
    float* pred = act  + (size_t)BB * CC * NN;                // [B,C,D]
    float* err  = pred + (size_t)BB * CC * DD;                // [B,C,D]

    boost_kernel<<<(CC * NN + 255) / 256, 256>>>(avg);

    dim3 g1(NN / 128, BB / 128, CC);
    drive_gemm<<<g1, 256>>>(x_in, x_ctx, Wff, Wctx, bias, act);

    topk_pred<<<BB * CC / 8, 256>>>(kptr, x_in, x_ctx, Wff, Wctx, bias,
                                    Wpred, act, pred, err);
}

// round 16
// speedup vs baseline: 1.6350x; 1.0199x over previous
#include <cuda_runtime.h>
#include <cuda_bf16.h>
#include <math.h>

#define BB 1024
#define CC 64
#define DD 256
#define NN 512
#define K2 (2*DD)

__device__ uint2 g_A2[BB * (K2/2)];   // packed {hi2, lo2} bf16, 0.3 folded into ctx half
__device__ float g_boost[CC*NN];

// ---------------------------------------------------------------------------
// Kernel 0: boost[c,n] = log1p(0.05/(avg+1e-6))   (batch-independent)
// ---------------------------------------------------------------------------
__global__ void boost_kernel(const float* __restrict__ avg) {
    int i = blockIdx.x * blockDim.x + threadIdx.x;
    if (i < CC * NN) g_boost[i] = log1pf(0.05f / (avg[i] + 1e-6f));
}

// ---- bf16 hi/lo split of a k-adjacent pair -> packed {hi2, lo2} ----
__device__ __forceinline__ uint2 bsplit2(float x, float y) {
    __nv_bfloat162 h = __floats2bfloat162_rn(x, y);
    float rx = x - __bfloat162float(h.x);
    float ry = y - __bfloat162float(h.y);
    __nv_bfloat162 l = __floats2bfloat162_rn(rx, ry);
    uint2 r;
    r.x = *reinterpret_cast<unsigned*>(&h);
    r.y = *reinterpret_cast<unsigned*>(&l);
    return r;
}

__device__ __forceinline__ void mma_bf16(
    float* cp, unsigned a0, unsigned a1, unsigned a2, unsigned a3,
    unsigned b0, unsigned b1)
{
    asm("mma.sync.aligned.m16n8k16.row.col.f32.bf16.bf16.f32 "
        "{%0,%1,%2,%3},{%4,%5,%6,%7},{%8,%9},{%0,%1,%2,%3};"
        : "+f"(cp[0]), "+f"(cp[1]), "+f"(cp[2]), "+f"(cp[3])
        : "r"(a0), "r"(a1), "r"(a2), "r"(a3), "r"(b0), "r"(b1));
}

// ---------------------------------------------------------------------------
// prep_A: pack x (stacked, 0.3 folded) into bf16 hi/lo k-pairs.
// ---------------------------------------------------------------------------
__global__ void prep_A(const float* __restrict__ x_in, const float* __restrict__ x_ctx) {
    int i = blockIdx.x * blockDim.x + threadIdx.x;   // over BB * 256 k-pairs
    if (i < BB * (K2/2)) {
        int b  = i >> 8;
        int k  = (i & 255) * 2;
        float v0, v1;
        if (k < DD) {
            v0 = x_in[(b << 8) + k];
            v1 = x_in[(b << 8) + k + 1];
        } else {
            v0 = 0.3f * x_ctx[(b << 8) + k - DD];
            v1 = 0.3f * x_ctx[(b << 8) + k + 1 - DD];
        }
        g_A2[i] = bsplit2(v0, v1);
    }
}

// ---------------------------------------------------------------------------
// Kernel 1: drive GEMM via 3xBF16 (m16n8k16). Round-14 skeleton; A now loads
// pre-packed uint2 planes (no split/scale in-kernel), B split in-loop at STS.
// ---------------------------------------------------------------------------
#define LD2 132

__global__ __launch_bounds__(256) void drive_gemm(
    const float* __restrict__ Wff,  const float* __restrict__ Wctx,
    const float* __restrict__ bias, float* __restrict__ act)
{
    __shared__ uint2 A2s[2][8][LD2];   // [buf][k2][m]  {hi2, lo2}
    __shared__ uint2 B2s[2][8][LD2];   // [buf][k2][n]

    int c  = blockIdx.z;
    int m0 = blockIdx.y * 128;
    int n0 = blockIdx.x * 128;
    int tid  = threadIdx.x;
    int warp = tid >> 5, lane = tid & 31;
    int wm = (warp & 1) * 64;
    int wn = (warp >> 1) * 32;
    int ar = lane >> 2;
    int ac = lane & 3;

    float acc[16][4];
    #pragma unroll
    for (int i = 0; i < 16; i++)
        #pragma unroll
        for (int j = 0; j < 4; j++) acc[i][j] = 0.f;

    const float* WffC  = Wff  + (size_t)c * DD * NN;
    const float* WctxC = Wctx + (size_t)c * DD * NN;
    const uint4* gA4   = reinterpret_cast<const uint4*>(g_A2);

    // B loader coords (1 slot/thread): two k-rows, 4 n
    int bk2 = tid >> 5, bnq = (tid & 31) << 2;

    // ---- preload k-tile 0 ----
    {
        #pragma unroll
        for (int i = 0; i < 2; i++) {
            int t = tid + i * 256;
            int m = t >> 2, kq2 = (t & 3) * 2;
            uint4 va = gA4[(size_t)(m0 + m) * 128 + (t & 3)];
            A2s[0][kq2    ][m] = make_uint2(va.x, va.y);
            A2s[0][kq2 + 1][m] = make_uint2(va.z, va.w);
        }
        const float* wp = WffC + (size_t)(2 * bk2) * NN + n0 + bnq;
        float4 r0 = *reinterpret_cast<const float4*>(wp);
        float4 r1 = *reinterpret_cast<const float4*>(wp + NN);
        B2s[0][bk2][bnq + 0] = bsplit2(r0.x, r1.x);
        B2s[0][bk2][bnq + 1] = bsplit2(r0.y, r1.y);
        B2s[0][bk2][bnq + 2] = bsplit2(r0.z, r1.z);
        B2s[0][bk2][bnq + 3] = bsplit2(r0.w, r1.w);
    }
    __syncthreads();

    int cur = 0;
    for (int kt = 0; kt < K2 / 16; kt++) {
        uint4  pa[2];
        float4 pb0, pb1;
        bool   has_next = (kt + 1 < K2 / 16);
        if (has_next) {
            int k0 = (kt + 1) * 16;
            #pragma unroll
            for (int i = 0; i < 2; i++) {
                int t = tid + i * 256;
                int m = t >> 2;
                pa[i] = gA4[(size_t)(m0 + m) * 128 + (size_t)(kt + 1) * 4 + (t & 3)];
            }
            const float* wsrc = (k0 < DD) ? (WffC + (size_t)k0 * NN)
                                          : (WctxC + (size_t)(k0 - DD) * NN);
            const float* wp = wsrc + (size_t)(2 * bk2) * NN + n0 + bnq;
            pb0 = *reinterpret_cast<const float4*>(wp);
            pb1 = *reinterpret_cast<const float4*>(wp + NN);
        }

        // ---- compute: one k16 step ----
        uint2 bf0[4], bf1[4];
        #pragma unroll
        for (int sn = 0; sn < 4; sn++) {
            int col = wn + sn * 8 + ar;
            bf0[sn] = B2s[cur][ac    ][col];
            bf1[sn] = B2s[cur][ac + 4][col];
        }
        #pragma unroll
        for (int sm = 0; sm < 4; sm++) {
            int mb = wm + sm * 16;
            uint2 A0 = A2s[cur][ac    ][mb + ar];
            uint2 A1 = A2s[cur][ac    ][mb + ar + 8];
            uint2 A2f = A2s[cur][ac + 4][mb + ar];
            uint2 A3 = A2s[cur][ac + 4][mb + ar + 8];
            #pragma unroll
            for (int sn = 0; sn < 4; sn++) {
                float* cp = acc[sm * 4 + sn];
                mma_bf16(cp, A0.x, A1.x, A2f.x, A3.x, bf0[sn].x, bf1[sn].x); // Ah*Bh
                mma_bf16(cp, A0.x, A1.x, A2f.x, A3.x, bf0[sn].y, bf1[sn].y); // Ah*Bl
                mma_bf16(cp, A0.y, A1.y, A2f.y, A3.y, bf0[sn].x, bf1[sn].x); // Al*Bh
            }
        }

        if (has_next) {
            int nxt = cur ^ 1;
            #pragma unroll
            for (int i = 0; i < 2; i++) {
                int t = tid + i * 256;
                int m = t >> 2, kq2 = (t & 3) * 2;
                A2s[nxt][kq2    ][m] = make_uint2(pa[i].x, pa[i].y);
                A2s[nxt][kq2 + 1][m] = make_uint2(pa[i].z, pa[i].w);
            }
            B2s[nxt][bk2][bnq + 0] = bsplit2(pb0.x, pb1.x);
            B2s[nxt][bk2][bnq + 1] = bsplit2(pb0.y, pb1.y);
            B2s[nxt][bk2][bnq + 2] = bsplit2(pb0.z, pb1.z);
            B2s[nxt][bk2][bnq + 3] = bsplit2(pb0.w, pb1.w);
            __syncthreads();
            cur = nxt;
        }
    }

    // ---- epilogue: + bias, scatter ----
    const float* bc = bias + (size_t)c * NN;
    #pragma unroll
    for (int sm = 0; sm < 4; sm++) {
        #pragma unroll
        for (int sn = 0; sn < 4; sn++) {
            const float* cp = acc[sm * 4 + sn];
            int col = n0 + wn + sn * 8 + ac * 2;
            float bx = bc[col], by = bc[col + 1];
            int r0 = m0 + wm + sm * 16 + ar;
            float2 v0 = make_float2(cp[0] + bx, cp[1] + by);
            float2 v1 = make_float2(cp[2] + bx, cp[3] + by);
            *reinterpret_cast<float2*>(act + ((size_t)r0 * CC + c) * NN + col)       = v0;
            *reinterpret_cast<float2*>(act + ((size_t)(r0 + 8) * CC + c) * NN + col) = v1;
        }
    }
}

// ---------------------------------------------------------------------------
// Kernel 2: warp-per-row k-WTA. Shortened bisection (window 2e-4) with
// asymmetric margin [Tf-4e-4, Tf+6e-4]; pred gather unrolled by 2.
// ---------------------------------------------------------------------------
__device__ __forceinline__ unsigned f2ord(float f) {
    unsigned u = __float_as_uint(f);
    return (u & 0x80000000u) ? ~u : (u | 0x80000000u);
}
__device__ __forceinline__ float ord2f(unsigned u) {
    unsigned v = (u & 0x80000000u) ? (u & 0x7FFFFFFFu) : ~u;
    return __uint_as_float(v);
}

__global__ __launch_bounds__(256, 4) void topk_pred(
    const int* __restrict__ kptr, const float* __restrict__ x_in,
    const float* __restrict__ x_ctx,
    const float* __restrict__ Wff, const float* __restrict__ Wctx,
    const float* __restrict__ bias,
    const float* __restrict__ Wp,
    float* __restrict__ act, float* __restrict__ pred, float* __restrict__ err)
{
    int lane = threadIdx.x & 31;
    int w    = threadIdx.x >> 5;
    int row  = blockIdx.x * 8 + w;          // b*C + c
    int c = row & (CC - 1);
    int b = row >> 6;

    __shared__ float s_vv[8][66];
    __shared__ int   s_ii[8][66];
    __shared__ int   s_bi[8][32];
    __shared__ float s_be[8][32];
    __shared__ unsigned s_bm[8][16];

    const float4* arow = reinterpret_cast<const float4*>(act + (size_t)row * NN);
    const float4* brow = reinterpret_cast<const float4*>(g_boost + (size_t)c * NN);

    float    f[16];
    unsigned u[16];
    #pragma unroll
    for (int i = 0; i < 4; i++) {
        float4 a  = arow[i * 32 + lane];
        float4 bo = brow[i * 32 + lane];
        f[i*4+0] = a.x; f[i*4+1] = a.y; f[i*4+2] = a.z; f[i*4+3] = a.w;
        u[i*4+0] = f2ord(a.x + bo.x);
        u[i*4+1] = f2ord(a.y + bo.y);
        u[i*4+2] = f2ord(a.z + bo.z);
        u[i*4+3] = f2ord(a.w + bo.w);
    }

    int k = *kptr;

    unsigned lmax = 0, lmin = 0xFFFFFFFFu;
    #pragma unroll
    for (int s = 0; s < 16; s++) { lmax = max(lmax, u[s]); lmin = min(lmin, u[s]); }
    unsigned mx = lmax, lb = lmax, gmn = lmin;
    #pragma unroll
    for (int o = 16; o; o >>= 1) {
        mx  = max(mx,  __shfl_xor_sync(0xffffffffu, mx,  o));
        lb  = min(lb,  __shfl_xor_sync(0xffffffffu, lb,  o));
        gmn = min(gmn, __shfl_xor_sync(0xffffffffu, gmn, o));
    }
    if (k > 32) lb = gmn;

    // bisection to window 2e-4; approx k-th ends in [lof, hif]
    float lof = ord2f(lb);
    float hif = ord2f(mx + 1u);
    int it = 0;
    while (hif - lof > 2.0e-4f && it < 40) {
        float midf = 0.5f * (lof + hif);
        unsigned Um = f2ord(midf);
        int cnt = 0;
        #pragma unroll
        for (int s = 0; s < 16; s++) cnt += (u[s] >= Um) ? 1 : 0;
        #pragma unroll
        for (int o = 16; o; o >>= 1) cnt += __shfl_xor_sync(0xffffffffu, cnt, o);
        if (cnt >= k) lof = midf; else hif = midf;
        it++;
    }
    float Tf = lof;
    // true k-th in [Tf - eps, Tf + 2e-4 + eps], eps <= 2e-4 (3xbf16) -> 2x headroom
    unsigned Uhi = f2ord(Tf + 6e-4f);
    unsigned Ulo = f2ord(Tf - 4e-4f);

    int nhi = 0, nbo = 0;
    #pragma unroll
    for (int s = 0; s < 16; s++) {
        nhi += (u[s] > Uhi) ? 1 : 0;
        nbo += (u[s] >= Ulo && u[s] <= Uhi) ? 1 : 0;
    }
    #pragma unroll
    for (int o = 16; o; o >>= 1) {
        nhi += __shfl_xor_sync(0xffffffffu, nhi, o);
        nbo += __shfl_xor_sync(0xffffffffu, nbo, o);
    }
    int r = k - nhi;

    bool win[16];
    if (nbo == r || nbo > 32) {
        unsigned Tcmp = (nbo > 32) ? f2ord(Tf) : Ulo;
        #pragma unroll
        for (int s = 0; s < 16; s++) win[s] = (u[s] >= Tcmp);
    } else {
        if (lane < 16) s_bm[w][lane] = 0u;
        int base = 0;
        #pragma unroll
        for (int i = 0; i < 4; i++) {
            #pragma unroll
            for (int q = 0; q < 4; q++) {
                int s = i * 4 + q;
                bool isb = (u[s] >= Ulo && u[s] <= Uhi);
                unsigned m = __ballot_sync(0xffffffffu, isb);
                if (isb) {
                    int pos = base + __popc(m & ((1u << lane) - 1u));
                    s_bi[w][pos] = i * 128 + lane * 4 + q;
                }
                base += __popc(m);
            }
        }
        __syncwarp();
        int mcnt = base;
        const float* xi = x_in  + (size_t)b * DD;
        const float* xc = x_ctx + (size_t)b * DD;
        for (int e = 0; e < mcnt; e++) {
            int ncol = s_bi[w][e];
            const float* wf = Wff  + ((size_t)c * DD) * NN + ncol;
            const float* wc = Wctx + ((size_t)c * DD) * NN + ncol;
            float aff = 0.f, act2 = 0.f;
            #pragma unroll
            for (int t = 0; t < 8; t++) {
                int d = lane + t * 32;
                aff  = fmaf(xi[d], wf[(size_t)d * NN], aff);
                act2 = fmaf(xc[d], wc[(size_t)d * NN], act2);
            }
            #pragma unroll
            for (int o = 16; o; o >>= 1) {
                aff  += __shfl_xor_sync(0xffffffffu, aff,  o);
                act2 += __shfl_xor_sync(0xffffffffu, act2, o);
            }
            if (lane == 0)
                s_be[w][e] = aff + act2 * 0.3f + bias[(size_t)c * NN + ncol]
                           + g_boost[(size_t)c * NN + ncol];
            __syncwarp();
        }
        if (lane < mcnt) {
            float v = s_be[w][lane];
            int g = 0;
            for (int j = 0; j < mcnt; j++) g += (s_be[w][j] > v) ? 1 : 0;
            if (g < r) {
                int col = s_bi[w][lane];
                atomicOr(&s_bm[w][col >> 5], 1u << (col & 31));
            }
        }
        __syncwarp();
        #pragma unroll
        for (int i = 0; i < 4; i++) {
            #pragma unroll
            for (int q = 0; q < 4; q++) {
                int s = i * 4 + q;
                int col = i * 128 + lane * 4 + q;
                bool inbm = (s_bm[w][col >> 5] >> (col & 31)) & 1u;
                win[s] = (u[s] > Uhi) || inbm;
            }
        }
    }

    float lsum = 0.f;
    #pragma unroll
    for (int s = 0; s < 16; s++) {
        float rl = fmaxf(f[s], 0.f);
        lsum += win[s] ? rl : 0.f;
    }
    #pragma unroll
    for (int o = 16; o; o >>= 1) lsum += __shfl_xor_sync(0xffffffffu, lsum, o);
    float scale = (float)k / (lsum + 1e-8f);

    float4* orow = reinterpret_cast<float4*>(act + (size_t)row * NN);
    int cnt_total = 0;
    #pragma unroll
    for (int i = 0; i < 4; i++) {
        float ov[4];
        #pragma unroll
        for (int q = 0; q < 4; q++) {
            int s = i * 4 + q;
            float rl  = fmaxf(f[s], 0.f);
            float val = win[s] ? rl * scale : 0.f;
            ov[q] = val;
            bool put = win[s] && (rl > 0.f);
            unsigned m = __ballot_sync(0xffffffffu, put);
            if (put) {
                int pos = cnt_total + __popc(m & ((1u << lane) - 1u));
                if (pos < 64) {
                    s_ii[w][pos] = i * 128 + lane * 4 + q;
                    s_vv[w][pos] = val;
                }
            }
            cnt_total += __popc(m);
        }
        orow[i * 32 + lane] = make_float4(ov[0], ov[1], ov[2], ov[3]);
    }
    if (cnt_total > 64) cnt_total = 64;
    // pad to even count for unrolled gather
    int cnt2 = (cnt_total + 1) & ~1;
    if (cnt_total + lane < cnt2) {
        s_vv[w][cnt_total + lane] = 0.f;
        s_ii[w][cnt_total + lane] = 0;
    }
    __syncwarp();

    const float* WpC = Wp + (size_t)c * NN * DD;
    float4 acc0 = make_float4(0.f, 0.f, 0.f, 0.f);
    float4 acc1 = make_float4(0.f, 0.f, 0.f, 0.f);
    for (int j = 0; j < cnt2; j += 2) {
        float vA = s_vv[w][j],     vB = s_vv[w][j + 1];
        const float4* rA = reinterpret_cast<const float4*>(WpC + (size_t)s_ii[w][j]     * DD);
        const float4* rB = reinterpret_cast<const float4*>(WpC + (size_t)s_ii[w][j + 1] * DD);
        float4 a0 = rA[lane], a1 = rA[lane + 32];
        float4 b0 = rB[lane], b1 = rB[lane + 32];
        acc0.x = fmaf(vA, a0.x, acc0.x); acc0.y = fmaf(vA, a0.y, acc0.y);
        acc0.z = fmaf(vA, a0.z, acc0.z); acc0.w = fmaf(vA, a0.w, acc0.w);
        acc1.x = fmaf(vA, a1.x, acc1.x); acc1.y = fmaf(vA, a1.y, acc1.y);
        acc1.z = fmaf(vA, a1.z, acc1.z); acc1.w = fmaf(vA, a1.w, acc1.w);
        acc0.x = fmaf(vB, b0.x, acc0.x); acc0.y = fmaf(vB, b0.y, acc0.y);
        acc0.z = fmaf(vB, b0.z, acc0.z); acc0.w = fmaf(vB, b0.w, acc0.w);
        acc1.x = fmaf(vB, b1.x, acc1.x); acc1.y = fmaf(vB, b1.y, acc1.y);
        acc1.z = fmaf(vB, b1.z, acc1.z); acc1.w = fmaf(vB, b1.w, acc1.w);
    }

    const float4* xr = reinterpret_cast<const float4*>(x_in + (size_t)b * DD);
    float4 x0 = xr[lane], x1 = xr[lane + 32];
    float4* prow = reinterpret_cast<float4*>(pred + (size_t)row * DD);
    float4* erow = reinterpret_cast<float4*>(err  + (size_t)row * DD);
    prow[lane]      = acc0;
    prow[lane + 32] = acc1;
    erow[lane]      = make_float4(x0.x - acc0.x, x0.y - acc0.y, x0.z - acc0.z, x0.w - acc0.w);
    erow[lane + 32] = make_float4(x1.x - acc1.x, x1.y - acc1.y, x1.z - acc1.z, x1.w - acc1.w);
}

// ---------------------------------------------------------------------------
extern "C" void kernel_launch(void* const* d_in, const int* in_sizes, int n_in,
                              void* d_out, int out_size)
{
    const float* x_in  = (const float*)d_in[0];
    const float* x_ctx = (const float*)d_in[1];
    const float* Wff   = (const float*)d_in[2];
    const float* Wctx  = (const float*)d_in[3];
    const float* Wpred = (const float*)d_in[4];
    const float* bias  = (const float*)d_in[5];
    const float* avg   = (const float*)d_in[6];
    const int*   kptr  = (const int*)d_in[7];

    float* act  = (float*)d_out;                              // [B,C,N]
    float* pred = act  + (size_t)BB * CC * NN;                // [B,C,D]
    float* err  = pred + (size_t)BB * CC * DD;                // [B,C,D]

    boost_kernel<<<(CC * NN + 255) / 256, 256>>>(avg);
    prep_A<<<(BB * (K2/2) + 255) / 256, 256>>>(x_in, x_ctx);

    dim3 g1(NN / 128, BB / 128, CC);
    drive_gemm<<<g1, 256>>>(Wff, Wctx, bias, act);

    topk_pred<<<BB * CC / 8, 256>>>(kptr, x_in, x_ctx, Wff, Wctx, bias,
                                    Wpred, act, pred, err);
}

// round 17
// speedup vs baseline: 1.6436x; 1.0052x over previous
#include <cuda_runtime.h>
#include <cuda_bf16.h>
#include <math.h>

#define BB 1024
#define CC 64
#define DD 256
#define NN 512
#define K2 (2*DD)

__device__ uint2 g_A2[BB * (K2/2)];   // packed {hi2, lo2} bf16, 0.3 folded into ctx half
__device__ float g_boost[CC*NN];

// ---------------------------------------------------------------------------
// Kernel 0: boost[c,n] = log1p(0.05/(avg+1e-6))   (batch-independent)
// ---------------------------------------------------------------------------
__global__ void boost_kernel(const float* __restrict__ avg) {
    int i = blockIdx.x * blockDim.x + threadIdx.x;
    if (i < CC * NN) g_boost[i] = log1pf(0.05f / (avg[i] + 1e-6f));
}

// ---- bf16 hi/lo split of a k-adjacent pair -> packed {hi2, lo2} ----
__device__ __forceinline__ uint2 bsplit2(float x, float y) {
    __nv_bfloat162 h = __floats2bfloat162_rn(x, y);
    float rx = x - __bfloat162float(h.x);
    float ry = y - __bfloat162float(h.y);
    __nv_bfloat162 l = __floats2bfloat162_rn(rx, ry);
    uint2 r;
    r.x = *reinterpret_cast<unsigned*>(&h);
    r.y = *reinterpret_cast<unsigned*>(&l);
    return r;
}

__device__ __forceinline__ void mma_bf16(
    float* cp, unsigned a0, unsigned a1, unsigned a2, unsigned a3,
    unsigned b0, unsigned b1)
{
    asm("mma.sync.aligned.m16n8k16.row.col.f32.bf16.bf16.f32 "
        "{%0,%1,%2,%3},{%4,%5,%6,%7},{%8,%9},{%0,%1,%2,%3};"
        : "+f"(cp[0]), "+f"(cp[1]), "+f"(cp[2]), "+f"(cp[3])
        : "r"(a0), "r"(a1), "r"(a2), "r"(a3), "r"(b0), "r"(b1));
}

// ---------------------------------------------------------------------------
// prep_A: pack x (stacked, 0.3 folded) into bf16 hi/lo k-pairs.
// ---------------------------------------------------------------------------
__global__ void prep_A(const float* __restrict__ x_in, const float* __restrict__ x_ctx) {
    int i = blockIdx.x * blockDim.x + threadIdx.x;
    if (i < BB * (K2/2)) {
        int b  = i >> 8;
        int k  = (i & 255) * 2;
        float v0, v1;
        if (k < DD) {
            v0 = x_in[(b << 8) + k];
            v1 = x_in[(b << 8) + k + 1];
        } else {
            v0 = 0.3f * x_ctx[(b << 8) + k - DD];
            v1 = 0.3f * x_ctx[(b << 8) + k + 1 - DD];
        }
        g_A2[i] = bsplit2(v0, v1);
    }
}

// ---------------------------------------------------------------------------
// Kernel 1: drive GEMM via 3xBF16 (m16n8k16) — EXACT round-16 kernel (369us,
// at the SIMT HMMA rt floor).
// ---------------------------------------------------------------------------
#define LD2 132

__global__ __launch_bounds__(256) void drive_gemm(
    const float* __restrict__ Wff,  const float* __restrict__ Wctx,
    const float* __restrict__ bias, float* __restrict__ act)
{
    __shared__ uint2 A2s[2][8][LD2];
    __shared__ uint2 B2s[2][8][LD2];

    int c  = blockIdx.z;
    int m0 = blockIdx.y * 128;
    int n0 = blockIdx.x * 128;
    int tid  = threadIdx.x;
    int warp = tid >> 5, lane = tid & 31;
    int wm = (warp & 1) * 64;
    int wn = (warp >> 1) * 32;
    int ar = lane >> 2;
    int ac = lane & 3;

    float acc[16][4];
    #pragma unroll
    for (int i = 0; i < 16; i++)
        #pragma unroll
        for (int j = 0; j < 4; j++) acc[i][j] = 0.f;

    const float* WffC  = Wff  + (size_t)c * DD * NN;
    const float* WctxC = Wctx + (size_t)c * DD * NN;
    const uint4* gA4   = reinterpret_cast<const uint4*>(g_A2);

    int bk2 = tid >> 5, bnq = (tid & 31) << 2;

    {
        #pragma unroll
        for (int i = 0; i < 2; i++) {
            int t = tid + i * 256;
            int m = t >> 2, kq2 = (t & 3) * 2;
            uint4 va = gA4[(size_t)(m0 + m) * 128 + (t & 3)];
            A2s[0][kq2    ][m] = make_uint2(va.x, va.y);
            A2s[0][kq2 + 1][m] = make_uint2(va.z, va.w);
        }
        const float* wp = WffC + (size_t)(2 * bk2) * NN + n0 + bnq;
        float4 r0 = *reinterpret_cast<const float4*>(wp);
        float4 r1 = *reinterpret_cast<const float4*>(wp + NN);
        B2s[0][bk2][bnq + 0] = bsplit2(r0.x, r1.x);
        B2s[0][bk2][bnq + 1] = bsplit2(r0.y, r1.y);
        B2s[0][bk2][bnq + 2] = bsplit2(r0.z, r1.z);
        B2s[0][bk2][bnq + 3] = bsplit2(r0.w, r1.w);
    }
    __syncthreads();

    int cur = 0;
    for (int kt = 0; kt < K2 / 16; kt++) {
        uint4  pa[2];
        float4 pb0, pb1;
        bool   has_next = (kt + 1 < K2 / 16);
        if (has_next) {
            int k0 = (kt + 1) * 16;
            #pragma unroll
            for (int i = 0; i < 2; i++) {
                int t = tid + i * 256;
                int m = t >> 2;
                pa[i] = gA4[(size_t)(m0 + m) * 128 + (size_t)(kt + 1) * 4 + (t & 3)];
            }
            const float* wsrc = (k0 < DD) ? (WffC + (size_t)k0 * NN)
                                          : (WctxC + (size_t)(k0 - DD) * NN);
            const float* wp = wsrc + (size_t)(2 * bk2) * NN + n0 + bnq;
            pb0 = *reinterpret_cast<const float4*>(wp);
            pb1 = *reinterpret_cast<const float4*>(wp + NN);
        }

        uint2 bf0[4], bf1[4];
        #pragma unroll
        for (int sn = 0; sn < 4; sn++) {
            int col = wn + sn * 8 + ar;
            bf0[sn] = B2s[cur][ac    ][col];
            bf1[sn] = B2s[cur][ac + 4][col];
        }
        #pragma unroll
        for (int sm = 0; sm < 4; sm++) {
            int mb = wm + sm * 16;
            uint2 A0 = A2s[cur][ac    ][mb + ar];
            uint2 A1 = A2s[cur][ac    ][mb + ar + 8];
            uint2 A2f = A2s[cur][ac + 4][mb + ar];
            uint2 A3 = A2s[cur][ac + 4][mb + ar + 8];
            #pragma unroll
            for (int sn = 0; sn < 4; sn++) {
                float* cp = acc[sm * 4 + sn];
                mma_bf16(cp, A0.x, A1.x, A2f.x, A3.x, bf0[sn].x, bf1[sn].x);
                mma_bf16(cp, A0.x, A1.x, A2f.x, A3.x, bf0[sn].y, bf1[sn].y);
                mma_bf16(cp, A0.y, A1.y, A2f.y, A3.y, bf0[sn].x, bf1[sn].x);
            }
        }

        if (has_next) {
            int nxt = cur ^ 1;
            #pragma unroll
            for (int i = 0; i < 2; i++) {
                int t = tid + i * 256;
                int m = t >> 2, kq2 = (t & 3) * 2;
                A2s[nxt][kq2    ][m] = make_uint2(pa[i].x, pa[i].y);
                A2s[nxt][kq2 + 1][m] = make_uint2(pa[i].z, pa[i].w);
            }
            B2s[nxt][bk2][bnq + 0] = bsplit2(pb0.x, pb1.x);
            B2s[nxt][bk2][bnq + 1] = bsplit2(pb0.y, pb1.y);
            B2s[nxt][bk2][bnq + 2] = bsplit2(pb0.z, pb1.z);
            B2s[nxt][bk2][bnq + 3] = bsplit2(pb0.w, pb1.w);
            __syncthreads();
            cur = nxt;
        }
    }

    const float* bc = bias + (size_t)c * NN;
    #pragma unroll
    for (int sm = 0; sm < 4; sm++) {
        #pragma unroll
        for (int sn = 0; sn < 4; sn++) {
            const float* cp = acc[sm * 4 + sn];
            int col = n0 + wn + sn * 8 + ac * 2;
            float bx = bc[col], by = bc[col + 1];
            int r0 = m0 + wm + sm * 16 + ar;
            float2 v0 = make_float2(cp[0] + bx, cp[1] + by);
            float2 v1 = make_float2(cp[2] + bx, cp[3] + by);
            *reinterpret_cast<float2*>(act + ((size_t)r0 * CC + c) * NN + col)       = v0;
            *reinterpret_cast<float2*>(act + ((size_t)(r0 + 8) * CC + c) * NN + col) = v1;
        }
    }
}

// ---------------------------------------------------------------------------
// Kernel 2: warp-per-row k-WTA. Float-domain bisection/margins (no f2ord),
// scan-based winner compaction. Margin [Tf-4e-4, Tf+6e-4] as round 16.
// ---------------------------------------------------------------------------
__device__ __forceinline__ unsigned f2ord(float f) {
    unsigned u = __float_as_uint(f);
    return (u & 0x80000000u) ? ~u : (u | 0x80000000u);
}
__device__ __forceinline__ float ord2f(unsigned u) {
    unsigned v = (u & 0x80000000u) ? (u & 0x7FFFFFFFu) : ~u;
    return __uint_as_float(v);
}

__global__ __launch_bounds__(256, 4) void topk_pred(
    const int* __restrict__ kptr, const float* __restrict__ x_in,
    const float* __restrict__ x_ctx,
    const float* __restrict__ Wff, const float* __restrict__ Wctx,
    const float* __restrict__ bias,
    const float* __restrict__ Wp,
    float* __restrict__ act, float* __restrict__ pred, float* __restrict__ err)
{
    int lane = threadIdx.x & 31;
    int w    = threadIdx.x >> 5;
    int row  = blockIdx.x * 8 + w;          // b*C + c
    int c = row & (CC - 1);
    int b = row >> 6;

    __shared__ float s_vv[8][66];
    __shared__ int   s_ii[8][66];
    __shared__ int   s_bi[8][32];
    __shared__ float s_be[8][32];
    __shared__ unsigned s_bm[8][16];

    const float4* arow = reinterpret_cast<const float4*>(act + (size_t)row * NN);
    const float4* brow = reinterpret_cast<const float4*>(g_boost + (size_t)c * NN);

    float f[16];    // drive
    float bf[16];   // boosted
    #pragma unroll
    for (int i = 0; i < 4; i++) {
        float4 a  = arow[i * 32 + lane];
        float4 bo = brow[i * 32 + lane];
        f[i*4+0] = a.x; f[i*4+1] = a.y; f[i*4+2] = a.z; f[i*4+3] = a.w;
        bf[i*4+0] = a.x + bo.x; bf[i*4+1] = a.y + bo.y;
        bf[i*4+2] = a.z + bo.z; bf[i*4+3] = a.w + bo.w;
    }

    int k = *kptr;

    // range bounds in float domain (no NaNs present)
    float lmax = -3.4e38f, lmin = 3.4e38f;
    #pragma unroll
    for (int s = 0; s < 16; s++) { lmax = fmaxf(lmax, bf[s]); lmin = fminf(lmin, bf[s]); }
    float mx = lmax, lb = lmax, gmn = lmin;
    #pragma unroll
    for (int o = 16; o; o >>= 1) {
        mx  = fmaxf(mx,  __shfl_xor_sync(0xffffffffu, mx,  o));
        lb  = fminf(lb,  __shfl_xor_sync(0xffffffffu, lb,  o));
        gmn = fminf(gmn, __shfl_xor_sync(0xffffffffu, gmn, o));
    }
    if (k > 32) lb = gmn;

    // bisection on floats to window 2e-4
    float lof = lb;
    float hif = ord2f(f2ord(mx) + 1u);   // strictly above max
    int it = 0;
    while (hif - lof > 2.0e-4f && it < 40) {
        float midf = 0.5f * (lof + hif);
        int cnt = 0;
        #pragma unroll
        for (int s = 0; s < 16; s++) cnt += (bf[s] >= midf) ? 1 : 0;
        #pragma unroll
        for (int o = 16; o; o >>= 1) cnt += __shfl_xor_sync(0xffffffffu, cnt, o);
        if (cnt >= k) lof = midf; else hif = midf;
        it++;
    }
    float Tf  = lof;
    float thi = Tf + 6e-4f;
    float tlo = Tf - 4e-4f;

    int nhi = 0, nbo = 0;
    #pragma unroll
    for (int s = 0; s < 16; s++) {
        nhi += (bf[s] > thi) ? 1 : 0;
        nbo += (bf[s] >= tlo && bf[s] <= thi) ? 1 : 0;
    }
    #pragma unroll
    for (int o = 16; o; o >>= 1) {
        nhi += __shfl_xor_sync(0xffffffffu, nhi, o);
        nbo += __shfl_xor_sync(0xffffffffu, nbo, o);
    }
    int r = k - nhi;

    bool win[16];
    if (nbo == r || nbo > 32) {
        float Tcmp = (nbo > 32) ? Tf : tlo;
        #pragma unroll
        for (int s = 0; s < 16; s++) win[s] = (bf[s] >= Tcmp);
    } else {
        // rare path: exact fp32 recompute of borderline elements
        if (lane < 16) s_bm[w][lane] = 0u;
        int base = 0;
        #pragma unroll
        for (int i = 0; i < 4; i++) {
            #pragma unroll
            for (int q = 0; q < 4; q++) {
                int s = i * 4 + q;
                bool isb = (bf[s] >= tlo && bf[s] <= thi);
                unsigned m = __ballot_sync(0xffffffffu, isb);
                if (isb) {
                    int pos = base + __popc(m & ((1u << lane) - 1u));
                    s_bi[w][pos] = i * 128 + lane * 4 + q;
                }
                base += __popc(m);
            }
        }
        __syncwarp();
        int mcnt = base;
        const float* xi = x_in  + (size_t)b * DD;
        const float* xc = x_ctx + (size_t)b * DD;
        for (int e = 0; e < mcnt; e++) {
            int ncol = s_bi[w][e];
            const float* wf = Wff  + ((size_t)c * DD) * NN + ncol;
            const float* wc = Wctx + ((size_t)c * DD) * NN + ncol;
            float aff = 0.f, act2 = 0.f;
            #pragma unroll
            for (int t = 0; t < 8; t++) {
                int d = lane + t * 32;
                aff  = fmaf(xi[d], wf[(size_t)d * NN], aff);
                act2 = fmaf(xc[d], wc[(size_t)d * NN], act2);
            }
            #pragma unroll
            for (int o = 16; o; o >>= 1) {
                aff  += __shfl_xor_sync(0xffffffffu, aff,  o);
                act2 += __shfl_xor_sync(0xffffffffu, act2, o);
            }
            if (lane == 0)
                s_be[w][e] = aff + act2 * 0.3f + bias[(size_t)c * NN + ncol]
                           + g_boost[(size_t)c * NN + ncol];
            __syncwarp();
        }
        if (lane < mcnt) {
            float v = s_be[w][lane];
            int g = 0;
            for (int j = 0; j < mcnt; j++) g += (s_be[w][j] > v) ? 1 : 0;
            if (g < r) {
                int col = s_bi[w][lane];
                atomicOr(&s_bm[w][col >> 5], 1u << (col & 31));
            }
        }
        __syncwarp();
        #pragma unroll
        for (int i = 0; i < 4; i++) {
            #pragma unroll
            for (int q = 0; q < 4; q++) {
                int s = i * 4 + q;
                int col = i * 128 + lane * 4 + q;
                bool inbm = (s_bm[w][col >> 5] >> (col & 31)) & 1u;
                win[s] = (bf[s] > thi) || inbm;
            }
        }
    }

    // normalization
    float lsum = 0.f;
    #pragma unroll
    for (int s = 0; s < 16; s++) {
        float rl = fmaxf(f[s], 0.f);
        lsum += win[s] ? rl : 0.f;
    }
    #pragma unroll
    for (int o = 16; o; o >>= 1) lsum += __shfl_xor_sync(0xffffffffu, lsum, o);
    float scale = (float)k / (lsum + 1e-8f);

    // write act; record put-mask; values into f[]
    float4* orow = reinterpret_cast<float4*>(act + (size_t)row * NN);
    unsigned pmask = 0;
    #pragma unroll
    for (int i = 0; i < 4; i++) {
        float ov[4];
        #pragma unroll
        for (int q = 0; q < 4; q++) {
            int s = i * 4 + q;
            float rl  = fmaxf(f[s], 0.f);
            float val = win[s] ? rl * scale : 0.f;
            ov[q] = val;
            f[s]  = val;
            if (win[s] && rl > 0.f) pmask |= (1u << s);
        }
        orow[i * 32 + lane] = make_float4(ov[0], ov[1], ov[2], ov[3]);
    }

    // warp exclusive scan of per-thread winner counts
    int mycnt = __popc(pmask);
    int inc = mycnt;
    #pragma unroll
    for (int o = 1; o < 32; o <<= 1) {
        int v = __shfl_up_sync(0xffffffffu, inc, o);
        if (lane >= o) inc += v;
    }
    int total = __shfl_sync(0xffffffffu, inc, 31);
    int p = inc - mycnt;
    #pragma unroll
    for (int s = 0; s < 16; s++) {
        if (pmask & (1u << s)) {
            if (p < 64) {
                s_ii[w][p] = (s >> 2) * 128 + lane * 4 + (s & 3);
                s_vv[w][p] = f[s];
            }
            p++;
        }
    }
    int cnt_total = total < 64 ? total : 64;
    int cnt2 = (cnt_total + 1) & ~1;
    if (cnt_total + lane < cnt2) {
        s_vv[w][cnt_total + lane] = 0.f;
        s_ii[w][cnt_total + lane] = 0;
    }
    __syncwarp();

    // sparse prediction + error (unrolled by 2)
    const float* WpC = Wp + (size_t)c * NN * DD;
    float4 acc0 = make_float4(0.f, 0.f, 0.f, 0.f);
    float4 acc1 = make_float4(0.f, 0.f, 0.f, 0.f);
    for (int j = 0; j < cnt2; j += 2) {
        float vA = s_vv[w][j],     vB = s_vv[w][j + 1];
        const float4* rA = reinterpret_cast<const float4*>(WpC + (size_t)s_ii[w][j]     * DD);
        const float4* rB = reinterpret_cast<const float4*>(WpC + (size_t)s_ii[w][j + 1] * DD);
        float4 a0 = rA[lane], a1 = rA[lane + 32];
        float4 b0 = rB[lane], b1 = rB[lane + 32];
        acc0.x = fmaf(vA, a0.x, acc0.x); acc0.y = fmaf(vA, a0.y, acc0.y);
        acc0.z = fmaf(vA, a0.z, acc0.z); acc0.w = fmaf(vA, a0.w, acc0.w);
        acc1.x = fmaf(vA, a1.x, acc1.x); acc1.y = fmaf(vA, a1.y, acc1.y);
        acc1.z = fmaf(vA, a1.z, acc1.z); acc1.w = fmaf(vA, a1.w, acc1.w);
        acc0.x = fmaf(vB, b0.x, acc0.x); acc0.y = fmaf(vB, b0.y, acc0.y);
        acc0.z = fmaf(vB, b0.z, acc0.z); acc0.w = fmaf(vB, b0.w, acc0.w);
        acc1.x = fmaf(vB, b1.x, acc1.x); acc1.y = fmaf(vB, b1.y, acc1.y);
        acc1.z = fmaf(vB, b1.z, acc1.z); acc1.w = fmaf(vB, b1.w, acc1.w);
    }

    const float4* xr = reinterpret_cast<const float4*>(x_in + (size_t)b * DD);
    float4 x0 = xr[lane], x1 = xr[lane + 32];
    float4* prow = reinterpret_cast<float4*>(pred + (size_t)row * DD);
    float4* erow = reinterpret_cast<float4*>(err  + (size_t)row * DD);
    prow[lane]      = acc0;
    prow[lane + 32] = acc1;
    erow[lane]      = make_float4(x0.x - acc0.x, x0.y - acc0.y, x0.z - acc0.z, x0.w - acc0.w);
    erow[lane + 32] = make_float4(x1.x - acc1.x, x1.y - acc1.y, x1.z - acc1.z, x1.w - acc1.w);
}

// ---------------------------------------------------------------------------
extern "C" void kernel_launch(void* const* d_in, const int* in_sizes, int n_in,
                              void* d_out, int out_size)
{
    const float* x_in  = (const float*)d_in[0];
    const float* x_ctx = (const float*)d_in[1];
    const float* Wff   = (const float*)d_in[2];
    const float* Wctx  = (const float*)d_in[3];
    const float* Wpred = (const float*)d_in[4];
    const float* bias  = (const float*)d_in[5];
    const float* avg   = (const float*)d_in[6];
    const int*   kptr  = (const int*)d_in[7];

    float* act  = (float*)d_out;                              // [B,C,N]
    float* pred = act  + (size_t)BB * CC * NN;                // [B,C,D]
    float* err  = pred + (size_t)BB * CC * DD;                // [B,C,D]

    boost_kernel<<<(CC * NN + 255) / 256, 256>>>(avg);
    prep_A<<<(BB * (K2/2) + 255) / 256, 256>>>(x_in, x_ctx);

    dim3 g1(NN / 128, BB / 128, CC);
    drive_gemm<<<g1, 256>>>(Wff, Wctx, bias, act);

    topk_pred<<<BB * CC / 8, 256>>>(kptr, x_in, x_ctx, Wff, Wctx, bias,
                                    Wpred, act, pred, err);
}